// round 12
// baseline (speedup 1.0000x reference)
#include <cuda_runtime.h>
#include <math.h>

#define TT 200
#define BB 128
#define FH 1024
#define PH 320
#define JH 512
#define VV 29
#define BLANKV 28
#define NSTEP 400
#define MAXL 256
#define YSN (NSTEP*BB*VV)
#define THR 640

// ---------------- device scratch ----------------
__device__ float  g_Fproj[(size_t)TT*BB*JH];
__device__ float4 g_xg0[VV*PH];                // [v][p][gate]
__device__ float4 g_wA [PH*PH];                // [k][p][gate]
__device__ float4 g_wB1[PH*PH];
__device__ float4 g_wB2[PH*PH];
__device__ float4 g_b1r[PH];
__device__ float  g_woT[VV*JH];

__device__ float g_h0[BB*PH], g_c0[BB*PH], g_h1[BB*PH], g_c1[BB*PH];
__device__ float g_h0n[BB*PH], g_c0n[BB*PH], g_h1n[BB*PH], g_c1n[BB*PH];
__device__ float g_jrelu[BB*JH];
__device__ int g_pre[BB], g_time[BB], g_olen[BB];
__device__ int g_tok[BB*MAXL];
__device__ unsigned g_eq[NSTEP];
__device__ unsigned g_done[NSTEP];
__device__ unsigned g_gcnt[4*32], g_grel[4*32];

__device__ __forceinline__ float sigf(float x){ return 1.0f/(1.0f+expf(-x)); }

__device__ __forceinline__ void barwait(unsigned* cnt, unsigned* rel, unsigned n){
    __syncthreads();
    if (threadIdx.x == 0){
        unsigned a;
        asm volatile("atom.add.release.gpu.global.u32 %0,[%1],1;"
                     : "=r"(a) : "l"(cnt) : "memory");
        a += 1u;
        if (a % n == 0u){
            asm volatile("red.release.gpu.global.max.u32 [%0],%1;"
                         :: "l"(rel), "r"(a) : "memory");
        } else {
            unsigned tgt = ((a + n - 1u)/n)*n;
            unsigned v;
            do {
                asm volatile("ld.acquire.gpu.global.u32 %0,[%1];"
                             : "=r"(v) : "l"(rel) : "memory");
            } while (v < tgt);
        }
    }
    __syncthreads();
}

__device__ __forceinline__ unsigned long long pack64(float lo, float hi){
    unsigned long long r;
    asm("mov.b64 %0,{%1,%2};" : "=l"(r) : "f"(lo), "f"(hi));
    return r;
}
__device__ __forceinline__ void unpack64(unsigned long long v, float& lo, float& hi){
    asm("mov.b64 {%0,%1},%2;" : "=f"(lo), "=f"(hi) : "l"(v));
}
__device__ __forceinline__ void fma2(unsigned long long& acc, unsigned long long a, unsigned long long b){
    asm("fma.rn.f32x2 %0,%1,%2,%0;" : "+l"(acc) : "l"(a), "l"(b));
}
__device__ __forceinline__ void add2(unsigned long long& acc, unsigned long long a){
    asm("add.rn.f32x2 %0,%0,%1;" : "+l"(acc) : "l"(a));
}

// ---------------- init + weight re-layouts ----------------
__global__ void rearr_init_kernel(const float* __restrict__ w_hh0, const float* __restrict__ w_ih1,
                                  const float* __restrict__ w_hh1, const float* __restrict__ b1,
                                  const float* __restrict__ w_o){
    int i = blockIdx.x*256 + threadIdx.x;
    if (i < BB*PH){ g_h0[i]=0.f; g_c0[i]=0.f; g_h1[i]=0.f; g_c1[i]=0.f; }
    if (i < BB){ g_pre[i]=0; g_time[i]=0; g_olen[i]=0; }
    if (i < BB*MAXL) g_tok[i] = BLANKV;
    if (i < NSTEP){ g_eq[i] = 0u; g_done[i] = 0u; }
    if (i < 4*32){ g_gcnt[i]=0u; g_grel[i]=0u; }
    const int Nt = PH*PH*4;
    if (i < Nt){
        int g = i & 3, p = (i >> 2) % PH, k = i / (PH*4);
        int src = k*(4*PH) + g*PH + p;
        ((float*)g_wA )[i] = w_hh0[src];
        ((float*)g_wB1)[i] = w_ih1[src];
        ((float*)g_wB2)[i] = w_hh1[src];
    }
    if (i < PH*4){
        int g = i & 3, p = i >> 2;
        ((float*)g_b1r)[i] = b1[g*PH + p];
    }
    if (i < VV*JH){
        int v = i / JH, k = i - v*JH;
        g_woT[i] = w_o[k*VV + v];
    }
}

// ---------------- xg0 ----------------
__global__ void xg0_kernel(const float* __restrict__ embed, const float* __restrict__ w_ih0,
                           const float* __restrict__ b0v){
    __shared__ float es[PH];
    int v = blockIdx.x;
    for (int k = threadIdx.x; k < PH; k += 256) es[k] = embed[v*PH + k];
    __syncthreads();
    for (int j = threadIdx.x; j < PH*4; j += 256){
        int p = j >> 2, g = j & 3;
        float a = b0v[g*PH + p];
        const float* w = w_ih0 + g*PH + p;
        for (int k = 0; k < PH; k++) a = fmaf(es[k], w[k*(4*PH)], a);
        ((float*)g_xg0)[v*PH*4 + j] = a;
    }
}

// ---------------- Fproj ----------------
__global__ void __launch_bounds__(256) fproj_kernel(const float* __restrict__ A,
                                                    const float* __restrict__ Bm,
                                                    const float* __restrict__ bj){
    const int N = JH, K = FH;
    __shared__ float Ast[2][16][68];
    __shared__ float Bs [2][16][68];
    int bm = blockIdx.y*64, bn = blockIdx.x*64;
    int tid = threadIdx.x;
    int tx = tid & 15, ty = tid >> 4;
    int lm = tid >> 2, lkq = tid & 3;
    int lk = tid >> 4, lnq = tid & 15;

    float acc[4][4];
#pragma unroll
    for (int i = 0; i < 4; i++)
#pragma unroll
        for (int j = 0; j < 4; j++) acc[i][j] = 0.f;

    float4 va = *(const float4*)(A + (size_t)(bm+lm)*K + lkq*4);
    float4 vb = *(const float4*)(Bm + (size_t)lk*N + bn + lnq*4);
    Ast[0][lkq*4+0][lm]=va.x; Ast[0][lkq*4+1][lm]=va.y;
    Ast[0][lkq*4+2][lm]=va.z; Ast[0][lkq*4+3][lm]=va.w;
    *(float4*)&Bs[0][lk][lnq*4] = vb;
    __syncthreads();

    int buf = 0;
    for (int k0 = 16; k0 < K; k0 += 16){
        va = *(const float4*)(A + (size_t)(bm+lm)*K + k0 + lkq*4);
        vb = *(const float4*)(Bm + (size_t)(k0+lk)*N + bn + lnq*4);
#pragma unroll
        for (int k = 0; k < 16; k++){
            float4 av = *(const float4*)&Ast[buf][k][ty*4];
            float4 bv = *(const float4*)&Bs [buf][k][tx*4];
            acc[0][0]=fmaf(av.x,bv.x,acc[0][0]); acc[0][1]=fmaf(av.x,bv.y,acc[0][1]);
            acc[0][2]=fmaf(av.x,bv.z,acc[0][2]); acc[0][3]=fmaf(av.x,bv.w,acc[0][3]);
            acc[1][0]=fmaf(av.y,bv.x,acc[1][0]); acc[1][1]=fmaf(av.y,bv.y,acc[1][1]);
            acc[1][2]=fmaf(av.y,bv.z,acc[1][2]); acc[1][3]=fmaf(av.y,bv.w,acc[1][3]);
            acc[2][0]=fmaf(av.z,bv.x,acc[2][0]); acc[2][1]=fmaf(av.z,bv.y,acc[2][1]);
            acc[2][2]=fmaf(av.z,bv.z,acc[2][2]); acc[2][3]=fmaf(av.z,bv.w,acc[2][3]);
            acc[3][0]=fmaf(av.w,bv.x,acc[3][0]); acc[3][1]=fmaf(av.w,bv.y,acc[3][1]);
            acc[3][2]=fmaf(av.w,bv.z,acc[3][2]); acc[3][3]=fmaf(av.w,bv.w,acc[3][3]);
        }
        int nb = buf ^ 1;
        Ast[nb][lkq*4+0][lm]=va.x; Ast[nb][lkq*4+1][lm]=va.y;
        Ast[nb][lkq*4+2][lm]=va.z; Ast[nb][lkq*4+3][lm]=va.w;
        *(float4*)&Bs[nb][lk][lnq*4] = vb;
        __syncthreads();
        buf = nb;
    }
#pragma unroll
    for (int k = 0; k < 16; k++){
        float4 av = *(const float4*)&Ast[buf][k][ty*4];
        float4 bv = *(const float4*)&Bs [buf][k][tx*4];
        acc[0][0]=fmaf(av.x,bv.x,acc[0][0]); acc[0][1]=fmaf(av.x,bv.y,acc[0][1]);
        acc[0][2]=fmaf(av.x,bv.z,acc[0][2]); acc[0][3]=fmaf(av.x,bv.w,acc[0][3]);
        acc[1][0]=fmaf(av.y,bv.x,acc[1][0]); acc[1][1]=fmaf(av.y,bv.y,acc[1][1]);
        acc[1][2]=fmaf(av.y,bv.z,acc[1][2]); acc[1][3]=fmaf(av.y,bv.w,acc[1][3]);
        acc[2][0]=fmaf(av.z,bv.x,acc[2][0]); acc[2][1]=fmaf(av.z,bv.y,acc[2][1]);
        acc[2][2]=fmaf(av.z,bv.z,acc[2][2]); acc[2][3]=fmaf(av.z,bv.w,acc[2][3]);
        acc[3][0]=fmaf(av.w,bv.x,acc[3][0]); acc[3][1]=fmaf(av.w,bv.y,acc[3][1]);
        acc[3][2]=fmaf(av.w,bv.z,acc[3][2]); acc[3][3]=fmaf(av.w,bv.w,acc[3][3]);
    }
#pragma unroll
    for (int i = 0; i < 4; i++)
#pragma unroll
        for (int j = 0; j < 4; j++){
            int n = bn + tx*4 + j;
            g_Fproj[(size_t)(bm + ty*4 + i)*N + n] = acc[i][j] + bj[n];
        }
}

// ================= persistent decode: 128 CTAs x 640 threads =================
#define SW_U2  3200
#define HSTR   324
#define SMH_F  (32*HSTR)

__global__ void __launch_bounds__(THR,1)
decode_kernel(const int* __restrict__ f_lens, const float* __restrict__ w_g,
              const float* __restrict__ b_o,
              float* __restrict__ out, int out_size){
    extern __shared__ float smem[];
    ulonglong2* swA2  = (ulonglong2*)smem;
    ulonglong2* swB12 = swA2  + SW_U2;
    ulonglong2* swB22 = swB12 + SW_U2;
    unsigned long long* swg2 = (unsigned long long*)(swB22 + SW_U2);  // [160 k2][16 j]
    float*  smh   = (float*)(swg2 + 160*16);
    ulonglong2* ppart = (ulonglong2*)smh;              // ALIAS: partials overwrite h tile
    float*  smy   = smh + SMH_F;
    int*    smnb  = (int*)(smy + 32);

    const int tid = threadIdx.x;
    const int cta = blockIdx.x;
    const int bb  = cta >> 5;
    const int sub = cta & 31;
    const int b0  = bb*32;
    const int lane = tid & 31, wrp = tid >> 5;
    // LSTM blocking: tid = ks*160 + pA*16 + bp   (4 ksplit, 10 p, 16 batch-pairs)
    const int ks  = tid / 160;
    const int r   = tid - ks*160;        // 0..159
    const int pA  = r >> 4;              // 0..9
    const int bp  = r & 15;              // 0..15
    const int p   = sub*10 + pA;
    const int bA  = b0 + 2*bp, bBt = bA + 1;
    const int k4beg = ks*20, k4end = ks*20 + 20;
    // phase C: 512 active; warp = (jp, bhalf), lane = (bidx, jsel)
    const int wc = wrp, jpc = wc >> 1, bhc = wc & 1;
    const int bidxc = lane >> 1, jselc = lane & 1;
    const int batc = bhc*16 + bidxc;
    const int jc = jpc*2 + jselc;
    const int bgc = b0 + batc;
    const int myb = cta;

    unsigned* mycnt = &g_gcnt[bb*32];
    unsigned* myrel = &g_grel[bb*32];

    // ---- one-time weight preload: k-pair gate-packed ----
    for (int i = tid; i < 1600; i += THR){
        int k2 = i/10, q = i - k2*10;
        int s0 = (2*k2)*PH + sub*10 + q, s1 = (2*k2+1)*PH + sub*10 + q;
        float4 a = g_wA[s0],  b = g_wA[s1];
        swA2[i*2+0] = make_ulonglong2(pack64(a.x,b.x), pack64(a.y,b.y));
        swA2[i*2+1] = make_ulonglong2(pack64(a.z,b.z), pack64(a.w,b.w));
        a = g_wB1[s0]; b = g_wB1[s1];
        swB12[i*2+0] = make_ulonglong2(pack64(a.x,b.x), pack64(a.y,b.y));
        swB12[i*2+1] = make_ulonglong2(pack64(a.z,b.z), pack64(a.w,b.w));
        a = g_wB2[s0]; b = g_wB2[s1];
        swB22[i*2+0] = make_ulonglong2(pack64(a.x,b.x), pack64(a.y,b.y));
        swB22[i*2+1] = make_ulonglong2(pack64(a.z,b.z), pack64(a.w,b.w));
    }
    for (int i = tid; i < 160*16; i += THR){
        int k2 = i >> 4, j = i & 15;
        swg2[i] = pack64(w_g[(size_t)(2*k2)*JH + sub*16 + j],
                         w_g[(size_t)(2*k2+1)*JH + sub*16 + j]);
    }
    __syncthreads();

    const ulonglong2* hrA = (const ulonglong2*)(smh + (2*bp)*HSTR);
    const ulonglong2* hrB = (const ulonglong2*)(smh + (2*bp+1)*HSTR);
    const ulonglong2* hrC = (const ulonglong2*)(smh + batc*HSTR);

    // float4 staging: 2560 float4s, 4 per thread
#define STAGE(SRC) do{                                                         \
        for (int e = tid; e < 2560; e += THR){                                 \
            int j_ = e/80, q_ = e - j_*80;                                     \
            *(float4*)(smh + j_*HSTR + q_*4) =                                 \
                __ldcg((const float4*)&(SRC)[(size_t)(b0+j_)*PH + q_*4]);      \
        } } while(0)

#define LSTM_K4(W)                                                             \
        for (int k4 = k4beg; k4 < k4end; k4++){                                \
            ulonglong2 hA = hrA[k4];                                           \
            ulonglong2 hB = hrB[k4];                                           \
            int base = k4*40 + pA*2;                                           \
            ulonglong2 w0 = (W)[base+0];                                       \
            ulonglong2 w1 = (W)[base+1];                                       \
            ulonglong2 w2 = (W)[base+20];                                      \
            ulonglong2 w3 = (W)[base+21];                                      \
            fma2(a0,hA.x,w0.x); fma2(a1,hA.x,w0.y); fma2(a2,hA.x,w1.x); fma2(a3,hA.x,w1.y); \
            fma2(a4,hB.x,w0.x); fma2(a5,hB.x,w0.y); fma2(a6,hB.x,w1.x); fma2(a7,hB.x,w1.y); \
            fma2(a0,hA.y,w2.x); fma2(a1,hA.y,w2.y); fma2(a2,hA.y,w3.x); fma2(a3,hA.y,w3.y); \
            fma2(a4,hB.y,w2.x); fma2(a5,hB.y,w2.y); fma2(a6,hB.y,w3.x); fma2(a7,hB.y,w3.y); \
        }

#define COMBINE_STORE() do{                                                    \
        __syncthreads();                                                       \
        if (ks > 0){                                                           \
            ulonglong2* ps = ppart + ((size_t)(ks-1)*160 + r)*4;               \
            ps[0] = make_ulonglong2(a0,a1); ps[1] = make_ulonglong2(a2,a3);    \
            ps[2] = make_ulonglong2(a4,a5); ps[3] = make_ulonglong2(a6,a7);    \
        }                                                                      \
        __syncthreads();                                                       \
        if (ks == 0){                                                          \
            for (int s = 0; s < 3; s++){                                       \
                const ulonglong2* ps = ppart + ((size_t)s*160 + r)*4;          \
                ulonglong2 q0 = ps[0], q1 = ps[1], q2 = ps[2], q3 = ps[3];     \
                add2(a0,q0.x); add2(a1,q0.y); add2(a2,q1.x); add2(a3,q1.y);    \
                add2(a4,q2.x); add2(a5,q2.y); add2(a6,q3.x); add2(a7,q3.y);    \
            }                                                                  \
        } } while(0)

    for (int step = 0; step < NSTEP; step++){
        // ============ phase A: LSTM0 ============
        STAGE(g_h0);
        __syncthreads();
        {
            unsigned long long a0,a1,a2,a3,a4,a5,a6,a7;
            if (ks == 0){
                float4 xA = g_xg0[__ldcg(&g_pre[bA])*PH + p];
                float4 xB = g_xg0[__ldcg(&g_pre[bBt])*PH + p];
                a0=pack64(xA.x,0.f); a1=pack64(xA.y,0.f); a2=pack64(xA.z,0.f); a3=pack64(xA.w,0.f);
                a4=pack64(xB.x,0.f); a5=pack64(xB.y,0.f); a6=pack64(xB.z,0.f); a7=pack64(xB.w,0.f);
            } else { a0=a1=a2=a3=a4=a5=a6=a7=0ull; }
#pragma unroll 2
            LSTM_K4(swA2);
            COMBINE_STORE();
            if (ks == 0){
                float l,h, gi,gf,gg,go;
                unpack64(a0,l,h); gi=l+h; unpack64(a1,l,h); gf=l+h;
                unpack64(a2,l,h); gg=l+h; unpack64(a3,l,h); go=l+h;
                float c  = __ldcg(&g_c0[bA*PH + p]);
                float cn = sigf(gf)*c + sigf(gi)*tanhf(gg);
                float hn = sigf(go)*tanhf(cn);
                __stcg(&g_c0n[bA*PH + p], cn);
                __stcg(&g_h0n[bA*PH + p], hn);
                unpack64(a4,l,h); gi=l+h; unpack64(a5,l,h); gf=l+h;
                unpack64(a6,l,h); gg=l+h; unpack64(a7,l,h); go=l+h;
                c  = __ldcg(&g_c0[bBt*PH + p]);
                cn = sigf(gf)*c + sigf(gi)*tanhf(gg);
                hn = sigf(go)*tanhf(cn);
                __stcg(&g_c0n[bBt*PH + p], cn);
                __stcg(&g_h0n[bBt*PH + p], hn);
            }
        }
        __syncthreads();   // protect ppart readers before next staging

        // ============ phase B: LSTM1 (pass0 on old h1 needs no barrier) ============
        {
            unsigned long long a0,a1,a2,a3,a4,a5,a6,a7;
            if (ks == 0){
                float4 bv = g_b1r[p];
                a0=pack64(bv.x,0.f); a1=pack64(bv.y,0.f); a2=pack64(bv.z,0.f); a3=pack64(bv.w,0.f);
                a4=a0; a5=a1; a6=a2; a7=a3;
            } else { a0=a1=a2=a3=a4=a5=a6=a7=0ull; }

            STAGE(g_h1);
            __syncthreads();
#pragma unroll 2
            LSTM_K4(swB22);

            barwait(mycnt, myrel, 32u);   // deferred A-completion barrier

            STAGE(g_h0n);
            __syncthreads();
#pragma unroll 2
            LSTM_K4(swB12);
            COMBINE_STORE();
            if (ks == 0){
                float l,h, gi,gf,gg,go;
                unpack64(a0,l,h); gi=l+h; unpack64(a1,l,h); gf=l+h;
                unpack64(a2,l,h); gg=l+h; unpack64(a3,l,h); go=l+h;
                float c  = __ldcg(&g_c1[bA*PH + p]);
                float cn = sigf(gf)*c + sigf(gi)*tanhf(gg);
                float hn = sigf(go)*tanhf(cn);
                __stcg(&g_c1n[bA*PH + p], cn);
                __stcg(&g_h1n[bA*PH + p], hn);
                unpack64(a4,l,h); gi=l+h; unpack64(a5,l,h); gf=l+h;
                unpack64(a6,l,h); gg=l+h; unpack64(a7,l,h); go=l+h;
                c  = __ldcg(&g_c1[bBt*PH + p]);
                cn = sigf(gf)*c + sigf(gi)*tanhf(gg);
                hn = sigf(go)*tanhf(cn);
                __stcg(&g_c1n[bBt*PH + p], cn);
                __stcg(&g_h1n[bBt*PH + p], hn);
            }
        }
        barwait(mycnt, myrel, 32u);

        // ============ phase C: jrelu = relu(Fproj[time[b]] + h1n @ w_g) ============
        STAGE(g_h1n);
        __syncthreads();
        if (tid < 512){
            unsigned long long p1 = 0ull;
#pragma unroll 4
            for (int k4 = 0; k4 < PH/4; k4++){
                ulonglong2 h2 = hrC[k4];
                fma2(p1, h2.x, swg2[(2*k4+0)*16 + jc]);
                fma2(p1, h2.y, swg2[(2*k4+1)*16 + jc]);
            }
            float lo, hi;
            unpack64(p1, lo, hi);
            int t = __ldcg(&g_time[bgc]);
            size_t fb = ((size_t)t*BB + bgc)*JH + sub*16 + jc;
            float r1 = __ldcg(&g_Fproj[fb]) + (lo + hi);
            __stcg(&g_jrelu[bgc*JH + sub*16 + jc], r1 > 0.f ? r1 : 0.f);
        }
        barwait(mycnt, myrel, 32u);

        // ============ phase D: logits + argmax + commit (CTA = batch) ============
        {
            for (int e = tid; e < JH; e += THR)
                smh[e] = __ldcg(&g_jrelu[myb*JH + e]);
            __syncthreads();
#pragma unroll
            for (int vi = 0; vi < 2; vi++){
                int v = wrp + vi*20;
                if (v < VV){
                    float a = 0.f;
#pragma unroll
                    for (int k = lane; k < JH; k += 32)
                        a = fmaf(smh[k], __ldcg(&g_woT[v*JH + k]), a);
#pragma unroll
                    for (int off = 16; off > 0; off >>= 1)
                        a += __shfl_xor_sync(0xffffffffu, a, off);
                    if (lane == 0) smy[v] = a + b_o[v];
                }
            }
            __syncthreads();
            if (tid < VV){
                int idx = (step*BB + myb)*VV + tid;
                if (idx < out_size) out[idx] = smy[tid];
            }
            if (tid == 0){
                int sym = 0; float best = smy[0];
                for (int v = 1; v < VV; v++) if (smy[v] > best){ best = smy[v]; sym = v; }
                int fin = 0;
                if (step > 0){
                    unsigned d;
                    do {
                        asm volatile("ld.acquire.gpu.global.u32 %0,[%1];"
                                     : "=r"(d) : "l"(&g_done[step-1]) : "memory");
                    } while (d < (unsigned)BB);
                    fin = (__ldcg(&g_eq[step-1]) == (unsigned)BB);
                }
                int nb  = (!fin) && (sym != BLANKV);
                int blk = (!fin) && (sym == BLANKV);
                if (nb){
                    int olen = g_olen[myb];
                    int pos = olen < (MAXL-1) ? olen : (MAXL-1);
                    g_tok[myb*MAXL + pos] = sym;
                    g_olen[myb] = olen + 1;
                    __stcg(&g_pre[myb], sym);
                }
                int tm  = __ldcg(&g_time[myb]);
                int eos = f_lens[myb] - 1;
                if (blk){ tm = tm + 1; if (tm > eos) tm = eos; }
                __stcg(&g_time[myb], tm);
                if (tm == eos) atomicAdd(&g_eq[step], 1u);
                unsigned du;
                asm volatile("atom.add.release.gpu.global.u32 %0,[%1],1;"
                             : "=r"(du) : "l"(&g_done[step]) : "memory");
                *smnb = nb;
            }
            __syncthreads();
            if (*smnb && tid < PH){
                int i = myb*PH + tid;
                __stcg(&g_h0[i], __ldcg(&g_h0n[i]));
                __stcg(&g_c0[i], __ldcg(&g_c0n[i]));
                __stcg(&g_h1[i], __ldcg(&g_h1n[i]));
                __stcg(&g_c1[i], __ldcg(&g_c1n[i]));
            }
        }
        barwait(mycnt, myrel, 32u);   // step boundary
    }

    // final: tokens + out_lens
    if (tid < MAXL){
        int idx = YSN + myb*MAXL + tid;
        if (idx < out_size) out[idx] = (float)g_tok[myb*MAXL + tid];
    }
    if (tid == 0){
        int idx = YSN + BB*MAXL + myb;
        if (idx < out_size) out[idx] = (float)g_olen[myb];
    }
#undef STAGE
#undef LSTM_K4
#undef COMBINE_STORE
}

extern "C" void kernel_launch(void* const* d_in, const int* in_sizes, int n_in,
                              void* d_out, int out_size){
    const float* f      = (const float*)d_in[0];
    const int*   f_lens = (const int*)  d_in[1];
    const float* embed  = (const float*)d_in[2];
    const float* w_ih0  = (const float*)d_in[3];
    const float* w_hh0  = (const float*)d_in[4];
    const float* b0     = (const float*)d_in[5];
    const float* w_ih1  = (const float*)d_in[6];
    const float* w_hh1  = (const float*)d_in[7];
    const float* b1     = (const float*)d_in[8];
    const float* w_f    = (const float*)d_in[9];
    const float* w_g    = (const float*)d_in[10];
    const float* b_j    = (const float*)d_in[11];
    const float* w_o    = (const float*)d_in[12];
    const float* b_o    = (const float*)d_in[13];
    float* out = (float*)d_out;

    // 153600 + 20480 + 41472 + 256 = 215,808 B
    const int smem_bytes = 3*51200 + 20480 + SMH_F*4 + 256;
    cudaFuncSetAttribute(decode_kernel, cudaFuncAttributeMaxDynamicSharedMemorySize, smem_bytes);

    rearr_init_kernel<<<1600, 256>>>(w_hh0, w_ih1, w_hh1, b1, w_o);
    xg0_kernel<<<VV, 256>>>(embed, w_ih0, b0);
    fproj_kernel<<<dim3(JH/64, (TT*BB)/64), 256>>>(f, w_f, b_j);
    decode_kernel<<<BB, THR, smem_bytes>>>(f_lens, w_g, b_o, out, out_size);
}

// round 13
// speedup vs baseline: 1.0460x; 1.0460x over previous
#include <cuda_runtime.h>
#include <math.h>

#define TT 200
#define BB 128
#define FH 1024
#define PH 320
#define JH 512
#define VV 29
#define BLANKV 28
#define NSTEP 400
#define MAXL 256
#define YSN (NSTEP*BB*VV)
#define THR 640

// ---------------- device scratch ----------------
__device__ float  g_Fproj[(size_t)TT*BB*JH];
__device__ float4 g_xg0[VV*PH];                // [v][p][gate]
__device__ float4 g_wA [PH*PH];                // [k][p][gate]
__device__ float4 g_wB1[PH*PH];
__device__ float4 g_wB2[PH*PH];
__device__ float4 g_b1r[PH];
__device__ float  g_woT[VV*JH];

__device__ float g_h0[BB*PH], g_c0[BB*PH], g_h1[BB*PH], g_c1[BB*PH];
__device__ float g_h0n[BB*PH], g_c0n[BB*PH], g_h1n[BB*PH], g_c1n[BB*PH];
__device__ float g_jrelu[BB*JH];
__device__ int g_pre[BB], g_time[BB], g_olen[BB];
__device__ int g_tok[BB*MAXL];
__device__ unsigned g_eq[NSTEP];
__device__ unsigned g_done[NSTEP];
__device__ unsigned g_gcnt[4*32], g_grel[4*32];

__device__ __forceinline__ float sigf(float x){ return 1.0f/(1.0f+expf(-x)); }

__device__ __forceinline__ void barwait(unsigned* cnt, unsigned* rel, unsigned n){
    __syncthreads();
    if (threadIdx.x == 0){
        unsigned a;
        asm volatile("atom.add.release.gpu.global.u32 %0,[%1],1;"
                     : "=r"(a) : "l"(cnt) : "memory");
        a += 1u;
        if (a % n == 0u){
            asm volatile("red.release.gpu.global.max.u32 [%0],%1;"
                         :: "l"(rel), "r"(a) : "memory");
        } else {
            unsigned tgt = ((a + n - 1u)/n)*n;
            unsigned v;
            do {
                asm volatile("ld.acquire.gpu.global.u32 %0,[%1];"
                             : "=r"(v) : "l"(rel) : "memory");
            } while (v < tgt);
        }
    }
    __syncthreads();
}

__device__ __forceinline__ unsigned long long pack64(float lo, float hi){
    unsigned long long r;
    asm("mov.b64 %0,{%1,%2};" : "=l"(r) : "f"(lo), "f"(hi));
    return r;
}
__device__ __forceinline__ void unpack64(unsigned long long v, float& lo, float& hi){
    asm("mov.b64 {%0,%1},%2;" : "=f"(lo), "=f"(hi) : "l"(v));
}
__device__ __forceinline__ void fma2(unsigned long long& acc, unsigned long long a, unsigned long long b){
    asm("fma.rn.f32x2 %0,%1,%2,%0;" : "+l"(acc) : "l"(a), "l"(b));
}
__device__ __forceinline__ void add2(unsigned long long& acc, unsigned long long a){
    asm("add.rn.f32x2 %0,%0,%1;" : "+l"(acc) : "l"(a));
}

// ---------------- init + weight re-layouts ----------------
__global__ void rearr_init_kernel(const float* __restrict__ w_hh0, const float* __restrict__ w_ih1,
                                  const float* __restrict__ w_hh1, const float* __restrict__ b1,
                                  const float* __restrict__ w_o){
    int i = blockIdx.x*256 + threadIdx.x;
    if (i < BB*PH){ g_h0[i]=0.f; g_c0[i]=0.f; g_h1[i]=0.f; g_c1[i]=0.f; }
    if (i < BB){ g_pre[i]=0; g_time[i]=0; g_olen[i]=0; }
    if (i < BB*MAXL) g_tok[i] = BLANKV;
    if (i < NSTEP){ g_eq[i] = 0u; g_done[i] = 0u; }
    if (i < 4*32){ g_gcnt[i]=0u; g_grel[i]=0u; }
    const int Nt = PH*PH*4;
    if (i < Nt){
        int g = i & 3, p = (i >> 2) % PH, k = i / (PH*4);
        int src = k*(4*PH) + g*PH + p;
        ((float*)g_wA )[i] = w_hh0[src];
        ((float*)g_wB1)[i] = w_ih1[src];
        ((float*)g_wB2)[i] = w_hh1[src];
    }
    if (i < PH*4){
        int g = i & 3, p = i >> 2;
        ((float*)g_b1r)[i] = b1[g*PH + p];
    }
    if (i < VV*JH){
        int v = i / JH, k = i - v*JH;
        g_woT[i] = w_o[k*VV + v];
    }
}

// ---------------- xg0 ----------------
__global__ void xg0_kernel(const float* __restrict__ embed, const float* __restrict__ w_ih0,
                           const float* __restrict__ b0v){
    __shared__ float es[PH];
    int v = blockIdx.x;
    for (int k = threadIdx.x; k < PH; k += 256) es[k] = embed[v*PH + k];
    __syncthreads();
    for (int j = threadIdx.x; j < PH*4; j += 256){
        int p = j >> 2, g = j & 3;
        float a = b0v[g*PH + p];
        const float* w = w_ih0 + g*PH + p;
        for (int k = 0; k < PH; k++) a = fmaf(es[k], w[k*(4*PH)], a);
        ((float*)g_xg0)[v*PH*4 + j] = a;
    }
}

// ---------------- Fproj ----------------
__global__ void __launch_bounds__(256) fproj_kernel(const float* __restrict__ A,
                                                    const float* __restrict__ Bm,
                                                    const float* __restrict__ bj){
    const int N = JH, K = FH;
    __shared__ float Ast[2][16][68];
    __shared__ float Bs [2][16][68];
    int bm = blockIdx.y*64, bn = blockIdx.x*64;
    int tid = threadIdx.x;
    int tx = tid & 15, ty = tid >> 4;
    int lm = tid >> 2, lkq = tid & 3;
    int lk = tid >> 4, lnq = tid & 15;

    float acc[4][4];
#pragma unroll
    for (int i = 0; i < 4; i++)
#pragma unroll
        for (int j = 0; j < 4; j++) acc[i][j] = 0.f;

    float4 va = *(const float4*)(A + (size_t)(bm+lm)*K + lkq*4);
    float4 vb = *(const float4*)(Bm + (size_t)lk*N + bn + lnq*4);
    Ast[0][lkq*4+0][lm]=va.x; Ast[0][lkq*4+1][lm]=va.y;
    Ast[0][lkq*4+2][lm]=va.z; Ast[0][lkq*4+3][lm]=va.w;
    *(float4*)&Bs[0][lk][lnq*4] = vb;
    __syncthreads();

    int buf = 0;
    for (int k0 = 16; k0 < K; k0 += 16){
        va = *(const float4*)(A + (size_t)(bm+lm)*K + k0 + lkq*4);
        vb = *(const float4*)(Bm + (size_t)(k0+lk)*N + bn + lnq*4);
#pragma unroll
        for (int k = 0; k < 16; k++){
            float4 av = *(const float4*)&Ast[buf][k][ty*4];
            float4 bv = *(const float4*)&Bs [buf][k][tx*4];
            acc[0][0]=fmaf(av.x,bv.x,acc[0][0]); acc[0][1]=fmaf(av.x,bv.y,acc[0][1]);
            acc[0][2]=fmaf(av.x,bv.z,acc[0][2]); acc[0][3]=fmaf(av.x,bv.w,acc[0][3]);
            acc[1][0]=fmaf(av.y,bv.x,acc[1][0]); acc[1][1]=fmaf(av.y,bv.y,acc[1][1]);
            acc[1][2]=fmaf(av.y,bv.z,acc[1][2]); acc[1][3]=fmaf(av.y,bv.w,acc[1][3]);
            acc[2][0]=fmaf(av.z,bv.x,acc[2][0]); acc[2][1]=fmaf(av.z,bv.y,acc[2][1]);
            acc[2][2]=fmaf(av.z,bv.z,acc[2][2]); acc[2][3]=fmaf(av.z,bv.w,acc[2][3]);
            acc[3][0]=fmaf(av.w,bv.x,acc[3][0]); acc[3][1]=fmaf(av.w,bv.y,acc[3][1]);
            acc[3][2]=fmaf(av.w,bv.z,acc[3][2]); acc[3][3]=fmaf(av.w,bv.w,acc[3][3]);
        }
        int nb = buf ^ 1;
        Ast[nb][lkq*4+0][lm]=va.x; Ast[nb][lkq*4+1][lm]=va.y;
        Ast[nb][lkq*4+2][lm]=va.z; Ast[nb][lkq*4+3][lm]=va.w;
        *(float4*)&Bs[nb][lk][lnq*4] = vb;
        __syncthreads();
        buf = nb;
    }
#pragma unroll
    for (int k = 0; k < 16; k++){
        float4 av = *(const float4*)&Ast[buf][k][ty*4];
        float4 bv = *(const float4*)&Bs [buf][k][tx*4];
        acc[0][0]=fmaf(av.x,bv.x,acc[0][0]); acc[0][1]=fmaf(av.x,bv.y,acc[0][1]);
        acc[0][2]=fmaf(av.x,bv.z,acc[0][2]); acc[0][3]=fmaf(av.x,bv.w,acc[0][3]);
        acc[1][0]=fmaf(av.y,bv.x,acc[1][0]); acc[1][1]=fmaf(av.y,bv.y,acc[1][1]);
        acc[1][2]=fmaf(av.y,bv.z,acc[1][2]); acc[1][3]=fmaf(av.y,bv.w,acc[1][3]);
        acc[2][0]=fmaf(av.z,bv.x,acc[2][0]); acc[2][1]=fmaf(av.z,bv.y,acc[2][1]);
        acc[2][2]=fmaf(av.z,bv.z,acc[2][2]); acc[2][3]=fmaf(av.z,bv.w,acc[2][3]);
        acc[3][0]=fmaf(av.w,bv.x,acc[3][0]); acc[3][1]=fmaf(av.w,bv.y,acc[3][1]);
        acc[3][2]=fmaf(av.w,bv.z,acc[3][2]); acc[3][3]=fmaf(av.w,bv.w,acc[3][3]);
    }
#pragma unroll
    for (int i = 0; i < 4; i++)
#pragma unroll
        for (int j = 0; j < 4; j++){
            int n = bn + tx*4 + j;
            g_Fproj[(size_t)(bm + ty*4 + i)*N + n] = acc[i][j] + bj[n];
        }
}

// ================= persistent decode: 128 CTAs x 640 threads =================
#define SW_U2  3200
#define HSTR   324
#define SMH_F  (32*HSTR)

__global__ void __launch_bounds__(THR,1)
decode_kernel(const int* __restrict__ f_lens, const float* __restrict__ w_g,
              const float* __restrict__ b_o,
              float* __restrict__ out, int out_size){
    extern __shared__ float smem[];
    ulonglong2* swA2  = (ulonglong2*)smem;
    ulonglong2* swB12 = swA2  + SW_U2;
    ulonglong2* swB22 = swB12 + SW_U2;
    unsigned long long* swg2 = (unsigned long long*)(swB22 + SW_U2);  // [160 k2][16 j]
    float*  smh   = (float*)(swg2 + 160*16);
    ulonglong2* ppart = (ulonglong2*)(smh + SMH_F);   // separate (as R10)
    float*  smy   = (float*)(ppart + 640);
    int*    smnb  = (int*)(smy + 32);                 // [0]=nb flag, [1]=fin flag

    const int tid = threadIdx.x;
    const int cta = blockIdx.x;
    const int bb  = cta >> 5;
    const int sub = cta & 31;
    const int b0  = bb*32;
    const int lane = tid & 31, wrp = tid >> 5;   // 0..19
    const int khalf = (tid >= 320);
    const int tidp  = khalf ? tid - 320 : tid;
    const int wrpp  = tidp >> 5;
    const int psel = lane & 1, bl4 = lane >> 1;
    const int bhalf = (wrpp < 5) ? 0 : 1, pduo = (wrpp < 5) ? wrpp : wrpp - 5;
    const int bat = bhalf*16 + bl4;
    const int lp  = pduo*2 + psel;
    const int p   = sub*10 + lp;
    const int bgl = b0 + bat;
    const int blc = lane, plc = wrp;             // phase C: plc<16 active
    const int bglc = b0 + blc;
    const int myb = cta;

    unsigned* mycnt = &g_gcnt[bb*32];
    unsigned* myrel = &g_grel[bb*32];

    // ---- one-time weight preload: k-pair gate-packed ----
    for (int i = tid; i < 1600; i += THR){
        int k2 = i/10, q = i - k2*10;
        int s0 = (2*k2)*PH + sub*10 + q, s1 = (2*k2+1)*PH + sub*10 + q;
        float4 a = g_wA[s0],  b = g_wA[s1];
        swA2[i*2+0] = make_ulonglong2(pack64(a.x,b.x), pack64(a.y,b.y));
        swA2[i*2+1] = make_ulonglong2(pack64(a.z,b.z), pack64(a.w,b.w));
        a = g_wB1[s0]; b = g_wB1[s1];
        swB12[i*2+0] = make_ulonglong2(pack64(a.x,b.x), pack64(a.y,b.y));
        swB12[i*2+1] = make_ulonglong2(pack64(a.z,b.z), pack64(a.w,b.w));
        a = g_wB2[s0]; b = g_wB2[s1];
        swB22[i*2+0] = make_ulonglong2(pack64(a.x,b.x), pack64(a.y,b.y));
        swB22[i*2+1] = make_ulonglong2(pack64(a.z,b.z), pack64(a.w,b.w));
    }
    for (int i = tid; i < 160*16; i += THR){
        int k2 = i >> 4, j = i & 15;
        swg2[i] = pack64(w_g[(size_t)(2*k2)*JH + sub*16 + j],
                         w_g[(size_t)(2*k2+1)*JH + sub*16 + j]);
    }
    __syncthreads();

    const ulonglong2* hrow2  = (const ulonglong2*)(smh + bat*HSTR);
    const ulonglong2* hrowc2 = (const ulonglong2*)(smh + blc*HSTR);
    const int k4beg = khalf*40, k4end = khalf*40 + 40;

    // float4 staging: 2560 float4s, 4 per thread
#define STAGE(SRC) do{                                                         \
        for (int e = tid; e < 2560; e += THR){                                 \
            int j_ = e/80, q_ = e - j_*80;                                     \
            *(float4*)(smh + j_*HSTR + q_*4) =                                 \
                __ldcg((const float4*)&(SRC)[(size_t)(b0+j_)*PH + q_*4]);      \
        } } while(0)

    for (int step = 0; step < NSTEP; step++){
        // ============ phase A: LSTM0 (k-split over 2 thread halves) ============
        STAGE(g_h0);
        __syncthreads();
        {
            unsigned long long a0, a1, a2, a3;
            if (!khalf){
                int pre = __ldcg(&g_pre[bgl]);
                float4 x0 = g_xg0[pre*PH + p];
                a0 = pack64(x0.x,0.f); a1 = pack64(x0.y,0.f);
                a2 = pack64(x0.z,0.f); a3 = pack64(x0.w,0.f);
            } else { a0 = a1 = a2 = a3 = 0ull; }
#pragma unroll 4
            for (int k4 = k4beg; k4 < k4end; k4++){
                ulonglong2 h2 = hrow2[k4];
                int base = k4*40 + lp*2;
                ulonglong2 wa0 = swA2[base+0];
                ulonglong2 wa1 = swA2[base+1];
                ulonglong2 wb0 = swA2[base+20];
                ulonglong2 wb1 = swA2[base+21];
                fma2(a0,h2.x,wa0.x); fma2(a1,h2.x,wa0.y); fma2(a2,h2.x,wa1.x); fma2(a3,h2.x,wa1.y);
                fma2(a0,h2.y,wb0.x); fma2(a1,h2.y,wb0.y); fma2(a2,h2.y,wb1.x); fma2(a3,h2.y,wb1.y);
            }
            if (khalf){
                ppart[tidp*2+0] = make_ulonglong2(a0, a1);
                ppart[tidp*2+1] = make_ulonglong2(a2, a3);
            }
            __syncthreads();
            if (!khalf){
                ulonglong2 q0 = ppart[tidp*2+0], q1 = ppart[tidp*2+1];
                add2(a0, q0.x); add2(a1, q0.y); add2(a2, q1.x); add2(a3, q1.y);
                float l0,h0v,l1,h1v,l2,h2v,l3,h3v;
                unpack64(a0,l0,h0v); unpack64(a1,l1,h1v); unpack64(a2,l2,h2v); unpack64(a3,l3,h3v);
                float gi=l0+h0v, gf=l1+h1v, gg=l2+h2v, go=l3+h3v;
                float c  = __ldcg(&g_c0[bgl*PH + p]);
                float cn = sigf(gf)*c + sigf(gi)*tanhf(gg);
                float hn = sigf(go)*tanhf(cn);
                __stcg(&g_c0n[bgl*PH + p], cn);
                __stcg(&g_h0n[bgl*PH + p], hn);
            }
        }
        // no barrier here — deferred to mid-B

        // ============ phase B: LSTM1 (pass0 on old h1, no barrier needed) ============
        {
            unsigned long long a0, a1, a2, a3;
            if (!khalf){
                float4 bv = g_b1r[p];
                a0 = pack64(bv.x,0.f); a1 = pack64(bv.y,0.f);
                a2 = pack64(bv.z,0.f); a3 = pack64(bv.w,0.f);
            } else { a0 = a1 = a2 = a3 = 0ull; }

            __syncthreads();   // phase-A smh readers done
            STAGE(g_h1);
            __syncthreads();
#pragma unroll 4
            for (int k4 = k4beg; k4 < k4end; k4++){
                ulonglong2 h2 = hrow2[k4];
                int base = k4*40 + lp*2;
                ulonglong2 wa0 = swB22[base+0];
                ulonglong2 wa1 = swB22[base+1];
                ulonglong2 wb0 = swB22[base+20];
                ulonglong2 wb1 = swB22[base+21];
                fma2(a0,h2.x,wa0.x); fma2(a1,h2.x,wa0.y); fma2(a2,h2.x,wa1.x); fma2(a3,h2.x,wa1.y);
                fma2(a0,h2.y,wb0.x); fma2(a1,h2.y,wb0.y); fma2(a2,h2.y,wb1.x); fma2(a3,h2.y,wb1.y);
            }

            barwait(mycnt, myrel, 32u);   // deferred A-completion barrier

            STAGE(g_h0n);
            __syncthreads();
#pragma unroll 4
            for (int k4 = k4beg; k4 < k4end; k4++){
                ulonglong2 h2 = hrow2[k4];
                int base = k4*40 + lp*2;
                ulonglong2 wa0 = swB12[base+0];
                ulonglong2 wa1 = swB12[base+1];
                ulonglong2 wb0 = swB12[base+20];
                ulonglong2 wb1 = swB12[base+21];
                fma2(a0,h2.x,wa0.x); fma2(a1,h2.x,wa0.y); fma2(a2,h2.x,wa1.x); fma2(a3,h2.x,wa1.y);
                fma2(a0,h2.y,wb0.x); fma2(a1,h2.y,wb0.y); fma2(a2,h2.y,wb1.x); fma2(a3,h2.y,wb1.y);
            }
            if (khalf){
                ppart[tidp*2+0] = make_ulonglong2(a0, a1);
                ppart[tidp*2+1] = make_ulonglong2(a2, a3);
            }
            __syncthreads();
            if (!khalf){
                ulonglong2 q0 = ppart[tidp*2+0], q1 = ppart[tidp*2+1];
                add2(a0, q0.x); add2(a1, q0.y); add2(a2, q1.x); add2(a3, q1.y);
                float l0,h0v,l1,h1v,l2,h2v,l3,h3v;
                unpack64(a0,l0,h0v); unpack64(a1,l1,h1v); unpack64(a2,l2,h2v); unpack64(a3,l3,h3v);
                float gi=l0+h0v, gf=l1+h1v, gg=l2+h2v, go=l3+h3v;
                float c  = __ldcg(&g_c1[bgl*PH + p]);
                float cn = sigf(gf)*c + sigf(gi)*tanhf(gg);
                float hn = sigf(go)*tanhf(cn);
                __stcg(&g_c1n[bgl*PH + p], cn);
                __stcg(&g_h1n[bgl*PH + p], hn);
            }
        }
        barwait(mycnt, myrel, 32u);

        // ============ phase C + overlapped done-poll ============
        STAGE(g_h1n);
        __syncthreads();
        if (tid == THR-1){
            // spare thread: poll step-1 completion + read eq while others compute
            int fin = 0;
            if (step > 0){
                unsigned d;
                do {
                    asm volatile("ld.acquire.gpu.global.u32 %0,[%1];"
                                 : "=r"(d) : "l"(&g_done[step-1]) : "memory");
                } while (d < (unsigned)BB);
                fin = (__ldcg(&g_eq[step-1]) == (unsigned)BB);
            }
            smnb[1] = fin;
        }
        if (plc < 16){
            unsigned long long p1 = 0ull;
#pragma unroll 4
            for (int k4 = 0; k4 < PH/4; k4++){
                ulonglong2 h2 = hrowc2[k4];
                fma2(p1, h2.x, swg2[(2*k4+0)*16 + plc]);
                fma2(p1, h2.y, swg2[(2*k4+1)*16 + plc]);
            }
            float lo, hi;
            unpack64(p1, lo, hi);
            int t = __ldcg(&g_time[bglc]);
            size_t fb = ((size_t)t*BB + bglc)*JH + sub*16 + plc;
            float r1 = __ldcg(&g_Fproj[fb]) + (lo + hi);
            __stcg(&g_jrelu[bglc*JH + sub*16 + plc], r1 > 0.f ? r1 : 0.f);
        }
        barwait(mycnt, myrel, 32u);

        // ============ phase D: logits + argmax + commit (CTA = batch) ============
        {
            const float* jr = &g_jrelu[(size_t)myb*JH];
#pragma unroll
            for (int vi = 0; vi < 2; vi++){
                int v = wrp + vi*20;
                if (v < VV){
                    float a = 0.f;
#pragma unroll
                    for (int k = lane; k < JH; k += 32)
                        a = fmaf(__ldcg(&jr[k]), __ldcg(&g_woT[v*JH + k]), a);
#pragma unroll
                    for (int off = 16; off > 0; off >>= 1)
                        a += __shfl_xor_sync(0xffffffffu, a, off);
                    if (lane == 0) smy[v] = a + b_o[v];
                }
            }
            __syncthreads();
            if (tid < VV){
                int idx = (step*BB + myb)*VV + tid;
                if (idx < out_size) out[idx] = smy[tid];
            }
            if (wrp == 0){
                // warp-parallel argmax (first-max tie-break)
                float val = (lane < VV) ? smy[lane] : __int_as_float(0xff800000);
                int   idx = lane;
#pragma unroll
                for (int off = 16; off > 0; off >>= 1){
                    float ov = __shfl_xor_sync(0xffffffffu, val, off);
                    int   oi = __shfl_xor_sync(0xffffffffu, idx, off);
                    if (ov > val || (ov == val && oi < idx)){ val = ov; idx = oi; }
                }
                if (lane == 0){
                    int sym = idx;
                    int fin = smnb[1];
                    int nb  = (!fin) && (sym != BLANKV);
                    int blk = (!fin) && (sym == BLANKV);
                    if (nb){
                        int olen = g_olen[myb];
                        int pos = olen < (MAXL-1) ? olen : (MAXL-1);
                        g_tok[myb*MAXL + pos] = sym;
                        g_olen[myb] = olen + 1;
                        __stcg(&g_pre[myb], sym);
                    }
                    int tm  = __ldcg(&g_time[myb]);
                    int eos = f_lens[myb] - 1;
                    if (blk){ tm = tm + 1; if (tm > eos) tm = eos; }
                    __stcg(&g_time[myb], tm);
                    if (tm == eos) atomicAdd(&g_eq[step], 1u);
                    unsigned du;
                    asm volatile("atom.add.release.gpu.global.u32 %0,[%1],1;"
                                 : "=r"(du) : "l"(&g_done[step]) : "memory");
                    smnb[0] = nb;
                }
            }
            __syncthreads();
            if (smnb[0] && tid < PH){
                int i = myb*PH + tid;
                __stcg(&g_h0[i], __ldcg(&g_h0n[i]));
                __stcg(&g_c0[i], __ldcg(&g_c0n[i]));
                __stcg(&g_h1[i], __ldcg(&g_h1n[i]));
                __stcg(&g_c1[i], __ldcg(&g_c1n[i]));
            }
        }
        barwait(mycnt, myrel, 32u);   // step boundary (group-local)
    }

    // final: tokens + out_lens
    if (tid < MAXL){
        int idx = YSN + myb*MAXL + tid;
        if (idx < out_size) out[idx] = (float)g_tok[myb*MAXL + tid];
    }
    if (tid == 0){
        int idx = YSN + BB*MAXL + myb;
        if (idx < out_size) out[idx] = (float)g_olen[myb];
    }
#undef STAGE
}

extern "C" void kernel_launch(void* const* d_in, const int* in_sizes, int n_in,
                              void* d_out, int out_size){
    const float* f      = (const float*)d_in[0];
    const int*   f_lens = (const int*)  d_in[1];
    const float* embed  = (const float*)d_in[2];
    const float* w_ih0  = (const float*)d_in[3];
    const float* w_hh0  = (const float*)d_in[4];
    const float* b0     = (const float*)d_in[5];
    const float* w_ih1  = (const float*)d_in[6];
    const float* w_hh1  = (const float*)d_in[7];
    const float* b1     = (const float*)d_in[8];
    const float* w_f    = (const float*)d_in[9];
    const float* w_g    = (const float*)d_in[10];
    const float* b_j    = (const float*)d_in[11];
    const float* w_o    = (const float*)d_in[12];
    const float* b_o    = (const float*)d_in[13];
    float* out = (float*)d_out;

    // 153600 + 20480 + 41472 + 10240 + 256 = 226,048 B
    const int smem_bytes = 3*51200 + 20480 + SMH_F*4 + 640*16 + 256;
    cudaFuncSetAttribute(decode_kernel, cudaFuncAttributeMaxDynamicSharedMemorySize, smem_bytes);

    rearr_init_kernel<<<1600, 256>>>(w_hh0, w_ih1, w_hh1, b1, w_o);
    xg0_kernel<<<VV, 256>>>(embed, w_ih0, b0);
    fproj_kernel<<<dim3(JH/64, (TT*BB)/64), 256>>>(f, w_f, b_j);
    decode_kernel<<<BB, THR, smem_bytes>>>(f_lens, w_g, b_o, out, out_size);
}

// round 14
// speedup vs baseline: 1.2024x; 1.1496x over previous
#include <cuda_runtime.h>
#include <math.h>

#define TT 200
#define BB 128
#define FH 1024
#define PH 320
#define JH 512
#define VV 29
#define BLANKV 28
#define NSTEP 400
#define MAXL 256
#define YSN (NSTEP*BB*VV)
#define THR 640

// ---------------- device scratch ----------------
__device__ float  g_Fproj[(size_t)TT*BB*JH];
__device__ float4 g_xg0[VV*PH];                // [v][p][gate]
__device__ float4 g_wA [PH*PH];                // [k][p][gate]
__device__ float4 g_wB1[PH*PH];
__device__ float4 g_wB2[PH*PH];
__device__ float4 g_b1r[PH];

__device__ float g_h0[BB*PH], g_c0[BB*PH], g_h1[BB*PH], g_c1[BB*PH];
__device__ float g_h0n[BB*PH], g_c0n[BB*PH], g_h1n[BB*PH], g_c1n[BB*PH];
__device__ float g_lpart[(size_t)BB*32*32];    // partial logits [b][sub][v(pad32)]
__device__ int g_pre[BB], g_time[BB], g_olen[BB];
__device__ int g_tok[BB*MAXL];
__device__ unsigned g_eq[NSTEP];
__device__ unsigned g_done[NSTEP];
__device__ unsigned g_gcnt[4*32], g_grel[4*32];

__device__ __forceinline__ float sigf(float x){ return 1.0f/(1.0f+expf(-x)); }

__device__ __forceinline__ void barwait(unsigned* cnt, unsigned* rel, unsigned n){
    __syncthreads();
    if (threadIdx.x == 0){
        unsigned a;
        asm volatile("atom.add.release.gpu.global.u32 %0,[%1],1;"
                     : "=r"(a) : "l"(cnt) : "memory");
        a += 1u;
        if (a % n == 0u){
            asm volatile("red.release.gpu.global.max.u32 [%0],%1;"
                         :: "l"(rel), "r"(a) : "memory");
        } else {
            unsigned tgt = ((a + n - 1u)/n)*n;
            unsigned v;
            do {
                asm volatile("ld.acquire.gpu.global.u32 %0,[%1];"
                             : "=r"(v) : "l"(rel) : "memory");
            } while (v < tgt);
        }
    }
    __syncthreads();
}

__device__ __forceinline__ unsigned long long pack64(float lo, float hi){
    unsigned long long r;
    asm("mov.b64 %0,{%1,%2};" : "=l"(r) : "f"(lo), "f"(hi));
    return r;
}
__device__ __forceinline__ void unpack64(unsigned long long v, float& lo, float& hi){
    asm("mov.b64 {%0,%1},%2;" : "=f"(lo), "=f"(hi) : "l"(v));
}
__device__ __forceinline__ void fma2(unsigned long long& acc, unsigned long long a, unsigned long long b){
    asm("fma.rn.f32x2 %0,%1,%2,%0;" : "+l"(acc) : "l"(a), "l"(b));
}
__device__ __forceinline__ void add2(unsigned long long& acc, unsigned long long a){
    asm("add.rn.f32x2 %0,%0,%1;" : "+l"(acc) : "l"(a));
}

// ---------------- init + weight re-layouts ----------------
__global__ void rearr_init_kernel(const float* __restrict__ w_hh0, const float* __restrict__ w_ih1,
                                  const float* __restrict__ w_hh1, const float* __restrict__ b1){
    int i = blockIdx.x*256 + threadIdx.x;
    if (i < BB*PH){ g_h0[i]=0.f; g_c0[i]=0.f; g_h1[i]=0.f; g_c1[i]=0.f; }
    if (i < BB){ g_pre[i]=0; g_time[i]=0; g_olen[i]=0; }
    if (i < BB*MAXL) g_tok[i] = BLANKV;
    if (i < NSTEP){ g_eq[i] = 0u; g_done[i] = 0u; }
    if (i < 4*32){ g_gcnt[i]=0u; g_grel[i]=0u; }
    const int Nt = PH*PH*4;
    if (i < Nt){
        int g = i & 3, p = (i >> 2) % PH, k = i / (PH*4);
        int src = k*(4*PH) + g*PH + p;
        ((float*)g_wA )[i] = w_hh0[src];
        ((float*)g_wB1)[i] = w_ih1[src];
        ((float*)g_wB2)[i] = w_hh1[src];
    }
    if (i < PH*4){
        int g = i & 3, p = i >> 2;
        ((float*)g_b1r)[i] = b1[g*PH + p];
    }
}

// ---------------- xg0 ----------------
__global__ void xg0_kernel(const float* __restrict__ embed, const float* __restrict__ w_ih0,
                           const float* __restrict__ b0v){
    __shared__ float es[PH];
    int v = blockIdx.x;
    for (int k = threadIdx.x; k < PH; k += 256) es[k] = embed[v*PH + k];
    __syncthreads();
    for (int j = threadIdx.x; j < PH*4; j += 256){
        int p = j >> 2, g = j & 3;
        float a = b0v[g*PH + p];
        const float* w = w_ih0 + g*PH + p;
        for (int k = 0; k < PH; k++) a = fmaf(es[k], w[k*(4*PH)], a);
        ((float*)g_xg0)[v*PH*4 + j] = a;
    }
}

// ---------------- Fproj ----------------
__global__ void __launch_bounds__(256) fproj_kernel(const float* __restrict__ A,
                                                    const float* __restrict__ Bm,
                                                    const float* __restrict__ bj){
    const int N = JH, K = FH;
    __shared__ float Ast[2][16][68];
    __shared__ float Bs [2][16][68];
    int bm = blockIdx.y*64, bn = blockIdx.x*64;
    int tid = threadIdx.x;
    int tx = tid & 15, ty = tid >> 4;
    int lm = tid >> 2, lkq = tid & 3;
    int lk = tid >> 4, lnq = tid & 15;

    float acc[4][4];
#pragma unroll
    for (int i = 0; i < 4; i++)
#pragma unroll
        for (int j = 0; j < 4; j++) acc[i][j] = 0.f;

    float4 va = *(const float4*)(A + (size_t)(bm+lm)*K + lkq*4);
    float4 vb = *(const float4*)(Bm + (size_t)lk*N + bn + lnq*4);
    Ast[0][lkq*4+0][lm]=va.x; Ast[0][lkq*4+1][lm]=va.y;
    Ast[0][lkq*4+2][lm]=va.z; Ast[0][lkq*4+3][lm]=va.w;
    *(float4*)&Bs[0][lk][lnq*4] = vb;
    __syncthreads();

    int buf = 0;
    for (int k0 = 16; k0 < K; k0 += 16){
        va = *(const float4*)(A + (size_t)(bm+lm)*K + k0 + lkq*4);
        vb = *(const float4*)(Bm + (size_t)(k0+lk)*N + bn + lnq*4);
#pragma unroll
        for (int k = 0; k < 16; k++){
            float4 av = *(const float4*)&Ast[buf][k][ty*4];
            float4 bv = *(const float4*)&Bs [buf][k][tx*4];
            acc[0][0]=fmaf(av.x,bv.x,acc[0][0]); acc[0][1]=fmaf(av.x,bv.y,acc[0][1]);
            acc[0][2]=fmaf(av.x,bv.z,acc[0][2]); acc[0][3]=fmaf(av.x,bv.w,acc[0][3]);
            acc[1][0]=fmaf(av.y,bv.x,acc[1][0]); acc[1][1]=fmaf(av.y,bv.y,acc[1][1]);
            acc[1][2]=fmaf(av.y,bv.z,acc[1][2]); acc[1][3]=fmaf(av.y,bv.w,acc[1][3]);
            acc[2][0]=fmaf(av.z,bv.x,acc[2][0]); acc[2][1]=fmaf(av.z,bv.y,acc[2][1]);
            acc[2][2]=fmaf(av.z,bv.z,acc[2][2]); acc[2][3]=fmaf(av.z,bv.w,acc[2][3]);
            acc[3][0]=fmaf(av.w,bv.x,acc[3][0]); acc[3][1]=fmaf(av.w,bv.y,acc[3][1]);
            acc[3][2]=fmaf(av.w,bv.z,acc[3][2]); acc[3][3]=fmaf(av.w,bv.w,acc[3][3]);
        }
        int nb = buf ^ 1;
        Ast[nb][lkq*4+0][lm]=va.x; Ast[nb][lkq*4+1][lm]=va.y;
        Ast[nb][lkq*4+2][lm]=va.z; Ast[nb][lkq*4+3][lm]=va.w;
        *(float4*)&Bs[nb][lk][lnq*4] = vb;
        __syncthreads();
        buf = nb;
    }
#pragma unroll
    for (int k = 0; k < 16; k++){
        float4 av = *(const float4*)&Ast[buf][k][ty*4];
        float4 bv = *(const float4*)&Bs [buf][k][tx*4];
        acc[0][0]=fmaf(av.x,bv.x,acc[0][0]); acc[0][1]=fmaf(av.x,bv.y,acc[0][1]);
        acc[0][2]=fmaf(av.x,bv.z,acc[0][2]); acc[0][3]=fmaf(av.x,bv.w,acc[0][3]);
        acc[1][0]=fmaf(av.y,bv.x,acc[1][0]); acc[1][1]=fmaf(av.y,bv.y,acc[1][1]);
        acc[1][2]=fmaf(av.y,bv.z,acc[1][2]); acc[1][3]=fmaf(av.y,bv.w,acc[1][3]);
        acc[2][0]=fmaf(av.z,bv.x,acc[2][0]); acc[2][1]=fmaf(av.z,bv.y,acc[2][1]);
        acc[2][2]=fmaf(av.z,bv.z,acc[2][2]); acc[2][3]=fmaf(av.z,bv.w,acc[2][3]);
        acc[3][0]=fmaf(av.w,bv.x,acc[3][0]); acc[3][1]=fmaf(av.w,bv.y,acc[3][1]);
        acc[3][2]=fmaf(av.w,bv.z,acc[3][2]); acc[3][3]=fmaf(av.w,bv.w,acc[3][3]);
    }
#pragma unroll
    for (int i = 0; i < 4; i++)
#pragma unroll
        for (int j = 0; j < 4; j++){
            int n = bn + tx*4 + j;
            g_Fproj[(size_t)(bm + ty*4 + i)*N + n] = acc[i][j] + bj[n];
        }
}

// ================= persistent decode: 128 CTAs x 640 threads =================
#define SW_U2  3200
#define HSTR   324
#define SMH_F  (32*HSTR)

__global__ void __launch_bounds__(THR,1)
decode_kernel(const int* __restrict__ f_lens, const float* __restrict__ w_g,
              const float* __restrict__ w_o, const float* __restrict__ b_o,
              float* __restrict__ out, int out_size){
    extern __shared__ float smem[];
    ulonglong2* swA2  = (ulonglong2*)smem;
    ulonglong2* swB12 = swA2  + SW_U2;
    ulonglong2* swB22 = swB12 + SW_U2;
    unsigned long long* swg2 = (unsigned long long*)(swB22 + SW_U2);  // [160 k2][16 j]
    float*  smh   = (float*)(swg2 + 160*16);
    ulonglong2* ppart = (ulonglong2*)(smh + SMH_F);   // LSTM k-split partials
    float*  ppartf = (float*)ppart;                   // ALIAS: phase-C jrelu slice [32][17]
    float*  wos   = (float*)(ppart + 640);            // w_o slice [16 j][29 v]
    float*  sred  = wos + 16*VV;                      // [4][32]
    int*    smnb  = (int*)(sred + 128);               // [0]=nb, [1]=fin

    const int tid = threadIdx.x;
    const int cta = blockIdx.x;
    const int bb  = cta >> 5;
    const int sub = cta & 31;
    const int b0  = bb*32;
    const int lane = tid & 31, wrp = tid >> 5;   // 0..19
    const int khalf = (tid >= 320);
    const int tidp  = khalf ? tid - 320 : tid;
    const int wrpp  = tidp >> 5;
    const int psel = lane & 1, bl4 = lane >> 1;
    const int bhalf = (wrpp < 5) ? 0 : 1, pduo = (wrpp < 5) ? wrpp : wrpp - 5;
    const int bat = bhalf*16 + bl4;
    const int lp  = pduo*2 + psel;
    const int p   = sub*10 + lp;
    const int bgl = b0 + bat;
    // phase C remap: 16 active warps, warp covers 2 j x 16 batches
    const int jlc  = (wrp >> 1)*2 + (lane & 1);      // 0..15 (warps 0..15)
    const int batc = (wrp & 1)*16 + (lane >> 1);     // 0..31
    const int myb = cta;

    unsigned* mycnt = &g_gcnt[bb*32];
    unsigned* myrel = &g_grel[bb*32];

    // ---- one-time weight preload ----
    for (int i = tid; i < 1600; i += THR){
        int k2 = i/10, q = i - k2*10;
        int s0 = (2*k2)*PH + sub*10 + q, s1 = (2*k2+1)*PH + sub*10 + q;
        float4 a = g_wA[s0],  b = g_wA[s1];
        swA2[i*2+0] = make_ulonglong2(pack64(a.x,b.x), pack64(a.y,b.y));
        swA2[i*2+1] = make_ulonglong2(pack64(a.z,b.z), pack64(a.w,b.w));
        a = g_wB1[s0]; b = g_wB1[s1];
        swB12[i*2+0] = make_ulonglong2(pack64(a.x,b.x), pack64(a.y,b.y));
        swB12[i*2+1] = make_ulonglong2(pack64(a.z,b.z), pack64(a.w,b.w));
        a = g_wB2[s0]; b = g_wB2[s1];
        swB22[i*2+0] = make_ulonglong2(pack64(a.x,b.x), pack64(a.y,b.y));
        swB22[i*2+1] = make_ulonglong2(pack64(a.z,b.z), pack64(a.w,b.w));
    }
    for (int i = tid; i < 160*16; i += THR){
        int k2 = i >> 4, j = i & 15;
        swg2[i] = pack64(w_g[(size_t)(2*k2)*JH + sub*16 + j],
                         w_g[(size_t)(2*k2+1)*JH + sub*16 + j]);
    }
    for (int i = tid; i < 16*VV; i += THR){
        int j = i / VV, v = i - j*VV;
        wos[i] = w_o[(size_t)(sub*16 + j)*VV + v];
    }
    __syncthreads();

    const ulonglong2* hrow2 = (const ulonglong2*)(smh + bat*HSTR);
    const ulonglong2* hrowc = (const ulonglong2*)(smh + batc*HSTR);
    const int k4beg = khalf*40, k4end = khalf*40 + 40;

#define STAGE(SRC) do{                                                         \
        for (int e = tid; e < 2560; e += THR){                                 \
            int j_ = e/80, q_ = e - j_*80;                                     \
            *(float4*)(smh + j_*HSTR + q_*4) =                                 \
                __ldcg((const float4*)&(SRC)[(size_t)(b0+j_)*PH + q_*4]);      \
        } } while(0)

    for (int step = 0; step < NSTEP; step++){
        // ============ phase A: LSTM0 (k-split over 2 halves) ============
        STAGE(g_h0);
        __syncthreads();
        {
            unsigned long long a0, a1, a2, a3;
            if (!khalf){
                int pre = __ldcg(&g_pre[bgl]);
                float4 x0 = g_xg0[pre*PH + p];
                a0 = pack64(x0.x,0.f); a1 = pack64(x0.y,0.f);
                a2 = pack64(x0.z,0.f); a3 = pack64(x0.w,0.f);
            } else { a0 = a1 = a2 = a3 = 0ull; }
#pragma unroll 4
            for (int k4 = k4beg; k4 < k4end; k4++){
                ulonglong2 h2 = hrow2[k4];
                int base = k4*40 + lp*2;
                ulonglong2 wa0 = swA2[base+0];
                ulonglong2 wa1 = swA2[base+1];
                ulonglong2 wb0 = swA2[base+20];
                ulonglong2 wb1 = swA2[base+21];
                fma2(a0,h2.x,wa0.x); fma2(a1,h2.x,wa0.y); fma2(a2,h2.x,wa1.x); fma2(a3,h2.x,wa1.y);
                fma2(a0,h2.y,wb0.x); fma2(a1,h2.y,wb0.y); fma2(a2,h2.y,wb1.x); fma2(a3,h2.y,wb1.y);
            }
            if (khalf){
                ppart[tidp*2+0] = make_ulonglong2(a0, a1);
                ppart[tidp*2+1] = make_ulonglong2(a2, a3);
            }
            __syncthreads();
            if (!khalf){
                ulonglong2 q0 = ppart[tidp*2+0], q1 = ppart[tidp*2+1];
                add2(a0, q0.x); add2(a1, q0.y); add2(a2, q1.x); add2(a3, q1.y);
                float l0,h0v,l1,h1v,l2,h2v,l3,h3v;
                unpack64(a0,l0,h0v); unpack64(a1,l1,h1v); unpack64(a2,l2,h2v); unpack64(a3,l3,h3v);
                float gi=l0+h0v, gf=l1+h1v, gg=l2+h2v, go=l3+h3v;
                float c  = __ldcg(&g_c0[bgl*PH + p]);
                float cn = sigf(gf)*c + sigf(gi)*tanhf(gg);
                float hn = sigf(go)*tanhf(cn);
                __stcg(&g_c0n[bgl*PH + p], cn);
                __stcg(&g_h0n[bgl*PH + p], hn);
            }
        }
        // no barrier — deferred to mid-B

        // ============ phase B: LSTM1 ============
        {
            unsigned long long a0, a1, a2, a3;
            if (!khalf){
                float4 bv = g_b1r[p];
                a0 = pack64(bv.x,0.f); a1 = pack64(bv.y,0.f);
                a2 = pack64(bv.z,0.f); a3 = pack64(bv.w,0.f);
            } else { a0 = a1 = a2 = a3 = 0ull; }

            __syncthreads();
            STAGE(g_h1);
            __syncthreads();
#pragma unroll 4
            for (int k4 = k4beg; k4 < k4end; k4++){
                ulonglong2 h2 = hrow2[k4];
                int base = k4*40 + lp*2;
                ulonglong2 wa0 = swB22[base+0];
                ulonglong2 wa1 = swB22[base+1];
                ulonglong2 wb0 = swB22[base+20];
                ulonglong2 wb1 = swB22[base+21];
                fma2(a0,h2.x,wa0.x); fma2(a1,h2.x,wa0.y); fma2(a2,h2.x,wa1.x); fma2(a3,h2.x,wa1.y);
                fma2(a0,h2.y,wb0.x); fma2(a1,h2.y,wb0.y); fma2(a2,h2.y,wb1.x); fma2(a3,h2.y,wb1.y);
            }

            barwait(mycnt, myrel, 32u);   // deferred A-completion barrier

            STAGE(g_h0n);
            __syncthreads();
#pragma unroll 4
            for (int k4 = k4beg; k4 < k4end; k4++){
                ulonglong2 h2 = hrow2[k4];
                int base = k4*40 + lp*2;
                ulonglong2 wa0 = swB12[base+0];
                ulonglong2 wa1 = swB12[base+1];
                ulonglong2 wb0 = swB12[base+20];
                ulonglong2 wb1 = swB12[base+21];
                fma2(a0,h2.x,wa0.x); fma2(a1,h2.x,wa0.y); fma2(a2,h2.x,wa1.x); fma2(a3,h2.x,wa1.y);
                fma2(a0,h2.y,wb0.x); fma2(a1,h2.y,wb0.y); fma2(a2,h2.y,wb1.x); fma2(a3,h2.y,wb1.y);
            }
            if (khalf){
                ppart[tidp*2+0] = make_ulonglong2(a0, a1);
                ppart[tidp*2+1] = make_ulonglong2(a2, a3);
            }
            __syncthreads();
            if (!khalf){
                ulonglong2 q0 = ppart[tidp*2+0], q1 = ppart[tidp*2+1];
                add2(a0, q0.x); add2(a1, q0.y); add2(a2, q1.x); add2(a3, q1.y);
                float l0,h0v,l1,h1v,l2,h2v,l3,h3v;
                unpack64(a0,l0,h0v); unpack64(a1,l1,h1v); unpack64(a2,l2,h2v); unpack64(a3,l3,h3v);
                float gi=l0+h0v, gf=l1+h1v, gg=l2+h2v, go=l3+h3v;
                float c  = __ldcg(&g_c1[bgl*PH + p]);
                float cn = sigf(gf)*c + sigf(gi)*tanhf(gg);
                float hn = sigf(go)*tanhf(cn);
                __stcg(&g_c1n[bgl*PH + p], cn);
                __stcg(&g_h1n[bgl*PH + p], hn);
            }
        }
        barwait(mycnt, myrel, 32u);

        // ============ phase C: jrelu slice (smem) + partial logits ============
        STAGE(g_h1n);
        __syncthreads();
        if (tid == THR-1){
            int fin = 0;
            if (step > 0){
                unsigned d;
                do {
                    asm volatile("ld.acquire.gpu.global.u32 %0,[%1];"
                                 : "=r"(d) : "l"(&g_done[step-1]) : "memory");
                } while (d < (unsigned)BB);
                fin = (__ldcg(&g_eq[step-1]) == (unsigned)BB);
            }
            smnb[1] = fin;
        }
        if (tid < 512){
            unsigned long long p1 = 0ull;
#pragma unroll 4
            for (int k4 = 0; k4 < PH/4; k4++){
                ulonglong2 h2 = hrowc[k4];
                fma2(p1, h2.x, swg2[(2*k4+0)*16 + jlc]);
                fma2(p1, h2.y, swg2[(2*k4+1)*16 + jlc]);
            }
            float lo, hi;
            unpack64(p1, lo, hi);
            int t = __ldcg(&g_time[b0 + batc]);
            float r1 = __ldcg(&g_Fproj[((size_t)t*BB + b0 + batc)*JH + sub*16 + jlc]) + (lo + hi);
            ppartf[batc*17 + jlc] = r1 > 0.f ? r1 : 0.f;
        }
        __syncthreads();
        for (int idx = tid; idx < 32*VV; idx += THR){
            int bl_ = idx / VV, v = idx - bl_*VV;
            float s = 0.f;
#pragma unroll
            for (int j = 0; j < 16; j++)
                s = fmaf(ppartf[bl_*17 + j], wos[j*VV + v], s);
            __stcg(&g_lpart[((size_t)(b0 + bl_)*32 + sub)*32 + v], s);
        }
        barwait(mycnt, myrel, 32u);

        // ============ phase D: reduce partials + argmax + commit ============
        {
            if (wrp < 4 && lane < VV){
                const float* lp_ = &g_lpart[((size_t)myb*32 + wrp*8)*32];
                float s = 0.f;
#pragma unroll
                for (int s8 = 0; s8 < 8; s8++)
                    s += __ldcg(&lp_[s8*32 + lane]);
                sred[wrp*32 + lane] = s;
            }
            __syncthreads();
            if (wrp == 0){
                float yv = __int_as_float(0xff800000);
                if (lane < VV){
                    yv = sred[lane] + sred[32+lane] + sred[64+lane] + sred[96+lane] + b_o[lane];
                    int idx = (step*BB + myb)*VV + lane;
                    if (idx < out_size) out[idx] = yv;
                }
                float val = yv; int ix = lane;
#pragma unroll
                for (int off = 16; off > 0; off >>= 1){
                    float ov = __shfl_xor_sync(0xffffffffu, val, off);
                    int   oi = __shfl_xor_sync(0xffffffffu, ix, off);
                    if (ov > val || (ov == val && oi < ix)){ val = ov; ix = oi; }
                }
                if (lane == 0){
                    int sym = ix;
                    int fin = smnb[1];
                    int nb  = (!fin) && (sym != BLANKV);
                    int blk = (!fin) && (sym == BLANKV);
                    if (nb){
                        int olen = g_olen[myb];
                        int pos = olen < (MAXL-1) ? olen : (MAXL-1);
                        g_tok[myb*MAXL + pos] = sym;
                        g_olen[myb] = olen + 1;
                        __stcg(&g_pre[myb], sym);
                    }
                    int tm  = __ldcg(&g_time[myb]);
                    int eos = f_lens[myb] - 1;
                    if (blk){ tm = tm + 1; if (tm > eos) tm = eos; }
                    __stcg(&g_time[myb], tm);
                    if (tm == eos) atomicAdd(&g_eq[step], 1u);
                    unsigned du;
                    asm volatile("atom.add.release.gpu.global.u32 %0,[%1],1;"
                                 : "=r"(du) : "l"(&g_done[step]) : "memory");
                    smnb[0] = nb;
                }
            }
            __syncthreads();
            if (smnb[0] && tid < PH){
                int i = myb*PH + tid;
                __stcg(&g_h0[i], __ldcg(&g_h0n[i]));
                __stcg(&g_c0[i], __ldcg(&g_c0n[i]));
                __stcg(&g_h1[i], __ldcg(&g_h1n[i]));
                __stcg(&g_c1[i], __ldcg(&g_c1n[i]));
            }
        }
        barwait(mycnt, myrel, 32u);   // step boundary
    }

    // final: tokens + out_lens
    if (tid < MAXL){
        int idx = YSN + myb*MAXL + tid;
        if (idx < out_size) out[idx] = (float)g_tok[myb*MAXL + tid];
    }
    if (tid == 0){
        int idx = YSN + BB*MAXL + myb;
        if (idx < out_size) out[idx] = (float)g_olen[myb];
    }
#undef STAGE
}

extern "C" void kernel_launch(void* const* d_in, const int* in_sizes, int n_in,
                              void* d_out, int out_size){
    const float* f      = (const float*)d_in[0];
    const int*   f_lens = (const int*)  d_in[1];
    const float* embed  = (const float*)d_in[2];
    const float* w_ih0  = (const float*)d_in[3];
    const float* w_hh0  = (const float*)d_in[4];
    const float* b0     = (const float*)d_in[5];
    const float* w_ih1  = (const float*)d_in[6];
    const float* w_hh1  = (const float*)d_in[7];
    const float* b1     = (const float*)d_in[8];
    const float* w_f    = (const float*)d_in[9];
    const float* w_g    = (const float*)d_in[10];
    const float* b_j    = (const float*)d_in[11];
    const float* w_o    = (const float*)d_in[12];
    const float* b_o    = (const float*)d_in[13];
    float* out = (float*)d_out;

    // 153600 + 20480 + 41472 + 10240 + wos 1856 + sred 512 + 64 = 228,224 B
    const int smem_bytes = 3*51200 + 20480 + SMH_F*4 + 640*16 + 16*VV*4 + 128*4 + 64;
    cudaFuncSetAttribute(decode_kernel, cudaFuncAttributeMaxDynamicSharedMemorySize, smem_bytes);

    rearr_init_kernel<<<1600, 256>>>(w_hh0, w_ih1, w_hh1, b1);
    xg0_kernel<<<VV, 256>>>(embed, w_ih0, b0);
    fproj_kernel<<<dim3(JH/64, (TT*BB)/64), 256>>>(f, w_f, b_j);
    decode_kernel<<<BB, THR, smem_bytes>>>(f_lens, w_g, w_o, b_o, out, out_size);
}

// round 15
// speedup vs baseline: 1.2111x; 1.0072x over previous
#include <cuda_runtime.h>
#include <math.h>

#define TT 200
#define BB 128
#define FH 1024
#define PH 320
#define JH 512
#define VV 29
#define BLANKV 28
#define NSTEP 400
#define MAXL 256
#define YSN (NSTEP*BB*VV)
#define THR 640

// ---------------- device scratch ----------------
__device__ float  g_Fproj[(size_t)TT*BB*JH];
__device__ float4 g_xg0[VV*PH];                // [v][p][gate]
__device__ float4 g_wA [PH*PH];                // [k][p][gate]
__device__ float4 g_wB1[PH*PH];
__device__ float4 g_wB2[PH*PH];
__device__ float4 g_b1r[PH];

__device__ float g_h0[BB*PH], g_c0[BB*PH], g_h1[BB*PH], g_c1[BB*PH];
__device__ float g_h0n[BB*PH], g_c0n[BB*PH], g_h1n[BB*PH], g_c1n[BB*PH];
__device__ float g_lpart[(size_t)BB*32*32];    // partial logits [b][sub][v(pad32)]
__device__ int g_pre[BB], g_time[BB], g_olen[BB];
__device__ int g_tok[BB*MAXL];
__device__ unsigned g_eq[NSTEP];
__device__ unsigned g_done[NSTEP];
__device__ unsigned g_gcnt[4*32], g_grel[4*32];

__device__ __forceinline__ float sigf(float x){ return 1.0f/(1.0f+expf(-x)); }

__device__ __forceinline__ void barwait(unsigned* cnt, unsigned* rel, unsigned n){
    __syncthreads();
    if (threadIdx.x == 0){
        unsigned a;
        asm volatile("atom.add.release.gpu.global.u32 %0,[%1],1;"
                     : "=r"(a) : "l"(cnt) : "memory");
        a += 1u;
        if (a % n == 0u){
            asm volatile("red.release.gpu.global.max.u32 [%0],%1;"
                         :: "l"(rel), "r"(a) : "memory");
        } else {
            unsigned tgt = ((a + n - 1u)/n)*n;
            unsigned v;
            do {
                asm volatile("ld.acquire.gpu.global.u32 %0,[%1];"
                             : "=r"(v) : "l"(rel) : "memory");
            } while (v < tgt);
        }
    }
    __syncthreads();
}

__device__ __forceinline__ unsigned long long pack64(float lo, float hi){
    unsigned long long r;
    asm("mov.b64 %0,{%1,%2};" : "=l"(r) : "f"(lo), "f"(hi));
    return r;
}
__device__ __forceinline__ void unpack64(unsigned long long v, float& lo, float& hi){
    asm("mov.b64 {%0,%1},%2;" : "=f"(lo), "=f"(hi) : "l"(v));
}
__device__ __forceinline__ void fma2(unsigned long long& acc, unsigned long long a, unsigned long long b){
    asm("fma.rn.f32x2 %0,%1,%2,%0;" : "+l"(acc) : "l"(a), "l"(b));
}
__device__ __forceinline__ void add2(unsigned long long& acc, unsigned long long a){
    asm("add.rn.f32x2 %0,%0,%1;" : "+l"(acc) : "l"(a));
}
__device__ __forceinline__ void cpa16(unsigned dst, const void* src){
    asm volatile("cp.async.cg.shared.global [%0], [%1], 16;" :: "r"(dst), "l"(src));
}

// ---------------- init + weight re-layouts ----------------
__global__ void rearr_init_kernel(const float* __restrict__ w_hh0, const float* __restrict__ w_ih1,
                                  const float* __restrict__ w_hh1, const float* __restrict__ b1){
    int i = blockIdx.x*256 + threadIdx.x;
    if (i < BB*PH){ g_h0[i]=0.f; g_c0[i]=0.f; g_h1[i]=0.f; g_c1[i]=0.f; }
    if (i < BB){ g_pre[i]=0; g_time[i]=0; g_olen[i]=0; }
    if (i < BB*MAXL) g_tok[i] = BLANKV;
    if (i < NSTEP){ g_eq[i] = 0u; g_done[i] = 0u; }
    if (i < 4*32){ g_gcnt[i]=0u; g_grel[i]=0u; }
    const int Nt = PH*PH*4;
    if (i < Nt){
        int g = i & 3, p = (i >> 2) % PH, k = i / (PH*4);
        int src = k*(4*PH) + g*PH + p;
        ((float*)g_wA )[i] = w_hh0[src];
        ((float*)g_wB1)[i] = w_ih1[src];
        ((float*)g_wB2)[i] = w_hh1[src];
    }
    if (i < PH*4){
        int g = i & 3, p = i >> 2;
        ((float*)g_b1r)[i] = b1[g*PH + p];
    }
}

// ---------------- xg0 ----------------
__global__ void xg0_kernel(const float* __restrict__ embed, const float* __restrict__ w_ih0,
                           const float* __restrict__ b0v){
    __shared__ float es[PH];
    int v = blockIdx.x;
    for (int k = threadIdx.x; k < PH; k += 256) es[k] = embed[v*PH + k];
    __syncthreads();
    for (int j = threadIdx.x; j < PH*4; j += 256){
        int p = j >> 2, g = j & 3;
        float a = b0v[g*PH + p];
        const float* w = w_ih0 + g*PH + p;
        for (int k = 0; k < PH; k++) a = fmaf(es[k], w[k*(4*PH)], a);
        ((float*)g_xg0)[v*PH*4 + j] = a;
    }
}

// ---------------- Fproj ----------------
__global__ void __launch_bounds__(256) fproj_kernel(const float* __restrict__ A,
                                                    const float* __restrict__ Bm,
                                                    const float* __restrict__ bj){
    const int N = JH, K = FH;
    __shared__ float Ast[2][16][68];
    __shared__ float Bs [2][16][68];
    int bm = blockIdx.y*64, bn = blockIdx.x*64;
    int tid = threadIdx.x;
    int tx = tid & 15, ty = tid >> 4;
    int lm = tid >> 2, lkq = tid & 3;
    int lk = tid >> 4, lnq = tid & 15;

    float acc[4][4];
#pragma unroll
    for (int i = 0; i < 4; i++)
#pragma unroll
        for (int j = 0; j < 4; j++) acc[i][j] = 0.f;

    float4 va = *(const float4*)(A + (size_t)(bm+lm)*K + lkq*4);
    float4 vb = *(const float4*)(Bm + (size_t)lk*N + bn + lnq*4);
    Ast[0][lkq*4+0][lm]=va.x; Ast[0][lkq*4+1][lm]=va.y;
    Ast[0][lkq*4+2][lm]=va.z; Ast[0][lkq*4+3][lm]=va.w;
    *(float4*)&Bs[0][lk][lnq*4] = vb;
    __syncthreads();

    int buf = 0;
    for (int k0 = 16; k0 < K; k0 += 16){
        va = *(const float4*)(A + (size_t)(bm+lm)*K + k0 + lkq*4);
        vb = *(const float4*)(Bm + (size_t)(k0+lk)*N + bn + lnq*4);
#pragma unroll
        for (int k = 0; k < 16; k++){
            float4 av = *(const float4*)&Ast[buf][k][ty*4];
            float4 bv = *(const float4*)&Bs [buf][k][tx*4];
            acc[0][0]=fmaf(av.x,bv.x,acc[0][0]); acc[0][1]=fmaf(av.x,bv.y,acc[0][1]);
            acc[0][2]=fmaf(av.x,bv.z,acc[0][2]); acc[0][3]=fmaf(av.x,bv.w,acc[0][3]);
            acc[1][0]=fmaf(av.y,bv.x,acc[1][0]); acc[1][1]=fmaf(av.y,bv.y,acc[1][1]);
            acc[1][2]=fmaf(av.y,bv.z,acc[1][2]); acc[1][3]=fmaf(av.y,bv.w,acc[1][3]);
            acc[2][0]=fmaf(av.z,bv.x,acc[2][0]); acc[2][1]=fmaf(av.z,bv.y,acc[2][1]);
            acc[2][2]=fmaf(av.z,bv.z,acc[2][2]); acc[2][3]=fmaf(av.z,bv.w,acc[2][3]);
            acc[3][0]=fmaf(av.w,bv.x,acc[3][0]); acc[3][1]=fmaf(av.w,bv.y,acc[3][1]);
            acc[3][2]=fmaf(av.w,bv.z,acc[3][2]); acc[3][3]=fmaf(av.w,bv.w,acc[3][3]);
        }
        int nb = buf ^ 1;
        Ast[nb][lkq*4+0][lm]=va.x; Ast[nb][lkq*4+1][lm]=va.y;
        Ast[nb][lkq*4+2][lm]=va.z; Ast[nb][lkq*4+3][lm]=va.w;
        *(float4*)&Bs[nb][lk][lnq*4] = vb;
        __syncthreads();
        buf = nb;
    }
#pragma unroll
    for (int k = 0; k < 16; k++){
        float4 av = *(const float4*)&Ast[buf][k][ty*4];
        float4 bv = *(const float4*)&Bs [buf][k][tx*4];
        acc[0][0]=fmaf(av.x,bv.x,acc[0][0]); acc[0][1]=fmaf(av.x,bv.y,acc[0][1]);
        acc[0][2]=fmaf(av.x,bv.z,acc[0][2]); acc[0][3]=fmaf(av.x,bv.w,acc[0][3]);
        acc[1][0]=fmaf(av.y,bv.x,acc[1][0]); acc[1][1]=fmaf(av.y,bv.y,acc[1][1]);
        acc[1][2]=fmaf(av.y,bv.z,acc[1][2]); acc[1][3]=fmaf(av.y,bv.w,acc[1][3]);
        acc[2][0]=fmaf(av.z,bv.x,acc[2][0]); acc[2][1]=fmaf(av.z,bv.y,acc[2][1]);
        acc[2][2]=fmaf(av.z,bv.z,acc[2][2]); acc[2][3]=fmaf(av.z,bv.w,acc[2][3]);
        acc[3][0]=fmaf(av.w,bv.x,acc[3][0]); acc[3][1]=fmaf(av.w,bv.y,acc[3][1]);
        acc[3][2]=fmaf(av.w,bv.z,acc[3][2]); acc[3][3]=fmaf(av.w,bv.w,acc[3][3]);
    }
#pragma unroll
    for (int i = 0; i < 4; i++)
#pragma unroll
        for (int j = 0; j < 4; j++){
            int n = bn + tx*4 + j;
            g_Fproj[(size_t)(bm + ty*4 + i)*N + n] = acc[i][j] + bj[n];
        }
}

// ================= persistent decode: 128 CTAs x 640 threads =================
#define SW_U2  3200
#define HSTR   324
#define SMH_F  (32*HSTR)

__global__ void __launch_bounds__(THR,1)
decode_kernel(const int* __restrict__ f_lens, const float* __restrict__ w_g,
              const float* __restrict__ w_o, const float* __restrict__ b_o,
              float* __restrict__ out, int out_size){
    extern __shared__ float smem[];
    ulonglong2* swA2  = (ulonglong2*)smem;
    ulonglong2* swB12 = swA2  + SW_U2;
    ulonglong2* swB22 = swB12 + SW_U2;
    unsigned long long* swg2 = (unsigned long long*)(swB22 + SW_U2);  // [160 k2][16 j]
    float*  smh   = (float*)(swg2 + 160*16);
    ulonglong2* ppart = (ulonglong2*)(smh + SMH_F);   // LSTM k-split partials
    float*  ppartf = (float*)ppart;                   // ALIAS: phase-C jrelu slice [32][17]
    float*  wos   = (float*)(ppart + 640);            // w_o slice [16 j][29 v]
    float*  sred  = wos + 16*VV;                      // [4][32]
    int*    smnb  = (int*)(sred + 128);               // [0]=nb, [1]=fin

    const int tid = threadIdx.x;
    const int cta = blockIdx.x;
    const int bb  = cta >> 5;
    const int sub = cta & 31;
    const int b0  = bb*32;
    const int lane = tid & 31, wrp = tid >> 5;   // 0..19
    const int khalf = (tid >= 320);
    const int tidp  = khalf ? tid - 320 : tid;
    const int wrpp  = tidp >> 5;
    const int psel = lane & 1, bl4 = lane >> 1;
    const int bhalf = (wrpp < 5) ? 0 : 1, pduo = (wrpp < 5) ? wrpp : wrpp - 5;
    const int bat = bhalf*16 + bl4;
    const int lp  = pduo*2 + psel;
    const int p   = sub*10 + lp;
    const int bgl = b0 + bat;
    // phase C remap: 16 active warps, warp covers 2 j x 16 batches
    const int jlc  = (wrp >> 1)*2 + (lane & 1);      // 0..15 (warps 0..15)
    const int batc = (wrp & 1)*16 + (lane >> 1);     // 0..31
    const int myb = cta;

    const unsigned smh_u32 = (unsigned)__cvta_generic_to_shared(smh);

    unsigned* mycnt = &g_gcnt[bb*32];
    unsigned* myrel = &g_grel[bb*32];

    // ---- one-time weight preload ----
    for (int i = tid; i < 1600; i += THR){
        int k2 = i/10, q = i - k2*10;
        int s0 = (2*k2)*PH + sub*10 + q, s1 = (2*k2+1)*PH + sub*10 + q;
        float4 a = g_wA[s0],  b = g_wA[s1];
        swA2[i*2+0] = make_ulonglong2(pack64(a.x,b.x), pack64(a.y,b.y));
        swA2[i*2+1] = make_ulonglong2(pack64(a.z,b.z), pack64(a.w,b.w));
        a = g_wB1[s0]; b = g_wB1[s1];
        swB12[i*2+0] = make_ulonglong2(pack64(a.x,b.x), pack64(a.y,b.y));
        swB12[i*2+1] = make_ulonglong2(pack64(a.z,b.z), pack64(a.w,b.w));
        a = g_wB2[s0]; b = g_wB2[s1];
        swB22[i*2+0] = make_ulonglong2(pack64(a.x,b.x), pack64(a.y,b.y));
        swB22[i*2+1] = make_ulonglong2(pack64(a.z,b.z), pack64(a.w,b.w));
    }
    for (int i = tid; i < 160*16; i += THR){
        int k2 = i >> 4, j = i & 15;
        swg2[i] = pack64(w_g[(size_t)(2*k2)*JH + sub*16 + j],
                         w_g[(size_t)(2*k2+1)*JH + sub*16 + j]);
    }
    for (int i = tid; i < 16*VV; i += THR){
        int j = i / VV, v = i - j*VV;
        wos[i] = w_o[(size_t)(sub*16 + j)*VV + v];
    }
    __syncthreads();

    const ulonglong2* hrow2 = (const ulonglong2*)(smh + bat*HSTR);
    const ulonglong2* hrowc = (const ulonglong2*)(smh + batc*HSTR);
    const int k4beg = khalf*40, k4end = khalf*40 + 40;

#define STAGE_ISSUE(SRC) do{                                                   \
        for (int e = tid; e < 2560; e += THR){                                 \
            int j_ = e/80, q_ = e - j_*80;                                     \
            cpa16(smh_u32 + (unsigned)(j_*HSTR + q_*4)*4u,                     \
                  &(SRC)[(size_t)(b0+j_)*PH + q_*4]);                          \
        }                                                                      \
        asm volatile("cp.async.commit_group;" ::: "memory"); } while(0)
#define STAGE_WAIT() do{ asm volatile("cp.async.wait_group 0;" ::: "memory"); \
                         __syncthreads(); } while(0)

    for (int step = 0; step < NSTEP; step++){
        // ============ phase A: LSTM0 (k-split over 2 halves) ============
        STAGE_ISSUE(g_h0);
        // --- hoisted dependent prefixes (off critical path) ---
        unsigned long long a0 = 0ull, a1 = 0ull, a2 = 0ull, a3 = 0ull;
        if (!khalf){
            int pre = __ldcg(&g_pre[bgl]);
            float4 x0 = g_xg0[pre*PH + p];
            a0 = pack64(x0.x,0.f); a1 = pack64(x0.y,0.f);
            a2 = pack64(x0.z,0.f); a3 = pack64(x0.w,0.f);
        }
        float fpv = 0.f;
        if (tid < 512){
            int t = __ldcg(&g_time[b0 + batc]);
            fpv = __ldcg(&g_Fproj[((size_t)t*BB + b0 + batc)*JH + sub*16 + jlc]);
        }
        STAGE_WAIT();
        {
#pragma unroll 4
            for (int k4 = k4beg; k4 < k4end; k4++){
                ulonglong2 h2 = hrow2[k4];
                int base = k4*40 + lp*2;
                ulonglong2 wa0 = swA2[base+0];
                ulonglong2 wa1 = swA2[base+1];
                ulonglong2 wb0 = swA2[base+20];
                ulonglong2 wb1 = swA2[base+21];
                fma2(a0,h2.x,wa0.x); fma2(a1,h2.x,wa0.y); fma2(a2,h2.x,wa1.x); fma2(a3,h2.x,wa1.y);
                fma2(a0,h2.y,wb0.x); fma2(a1,h2.y,wb0.y); fma2(a2,h2.y,wb1.x); fma2(a3,h2.y,wb1.y);
            }
            if (khalf){
                ppart[tidp*2+0] = make_ulonglong2(a0, a1);
                ppart[tidp*2+1] = make_ulonglong2(a2, a3);
            }
            __syncthreads();           // smh readers done; ppart visible
            STAGE_ISSUE(g_h1);         // overlap h1 stage with A tail
            if (!khalf){
                ulonglong2 q0 = ppart[tidp*2+0], q1 = ppart[tidp*2+1];
                add2(a0, q0.x); add2(a1, q0.y); add2(a2, q1.x); add2(a3, q1.y);
                float l0,h0v,l1,h1v,l2,h2v,l3,h3v;
                unpack64(a0,l0,h0v); unpack64(a1,l1,h1v); unpack64(a2,l2,h2v); unpack64(a3,l3,h3v);
                float gi=l0+h0v, gf=l1+h1v, gg=l2+h2v, go=l3+h3v;
                float c  = __ldcg(&g_c0[bgl*PH + p]);
                float cn = sigf(gf)*c + sigf(gi)*tanhf(gg);
                float hn = sigf(go)*tanhf(cn);
                __stcg(&g_c0n[bgl*PH + p], cn);
                __stcg(&g_h0n[bgl*PH + p], hn);
            }
        }

        // ============ phase B: LSTM1 (pass0 on old h1) ============
        {
            if (!khalf){
                float4 bv = g_b1r[p];
                a0 = pack64(bv.x,0.f); a1 = pack64(bv.y,0.f);
                a2 = pack64(bv.z,0.f); a3 = pack64(bv.w,0.f);
            } else { a0 = a1 = a2 = a3 = 0ull; }

            STAGE_WAIT();   // h1 ready
#pragma unroll 4
            for (int k4 = k4beg; k4 < k4end; k4++){
                ulonglong2 h2 = hrow2[k4];
                int base = k4*40 + lp*2;
                ulonglong2 wa0 = swB22[base+0];
                ulonglong2 wa1 = swB22[base+1];
                ulonglong2 wb0 = swB22[base+20];
                ulonglong2 wb1 = swB22[base+21];
                fma2(a0,h2.x,wa0.x); fma2(a1,h2.x,wa0.y); fma2(a2,h2.x,wa1.x); fma2(a3,h2.x,wa1.y);
                fma2(a0,h2.y,wb0.x); fma2(a1,h2.y,wb0.y); fma2(a2,h2.y,wb1.x); fma2(a3,h2.y,wb1.y);
            }

            barwait(mycnt, myrel, 32u);   // deferred A-completion barrier

            STAGE_ISSUE(g_h0n);
            STAGE_WAIT();
#pragma unroll 4
            for (int k4 = k4beg; k4 < k4end; k4++){
                ulonglong2 h2 = hrow2[k4];
                int base = k4*40 + lp*2;
                ulonglong2 wa0 = swB12[base+0];
                ulonglong2 wa1 = swB12[base+1];
                ulonglong2 wb0 = swB12[base+20];
                ulonglong2 wb1 = swB12[base+21];
                fma2(a0,h2.x,wa0.x); fma2(a1,h2.x,wa0.y); fma2(a2,h2.x,wa1.x); fma2(a3,h2.x,wa1.y);
                fma2(a0,h2.y,wb0.x); fma2(a1,h2.y,wb0.y); fma2(a2,h2.y,wb1.x); fma2(a3,h2.y,wb1.y);
            }
            if (khalf){
                ppart[tidp*2+0] = make_ulonglong2(a0, a1);
                ppart[tidp*2+1] = make_ulonglong2(a2, a3);
            }
            __syncthreads();
            if (!khalf){
                ulonglong2 q0 = ppart[tidp*2+0], q1 = ppart[tidp*2+1];
                add2(a0, q0.x); add2(a1, q0.y); add2(a2, q1.x); add2(a3, q1.y);
                float l0,h0v,l1,h1v,l2,h2v,l3,h3v;
                unpack64(a0,l0,h0v); unpack64(a1,l1,h1v); unpack64(a2,l2,h2v); unpack64(a3,l3,h3v);
                float gi=l0+h0v, gf=l1+h1v, gg=l2+h2v, go=l3+h3v;
                float c  = __ldcg(&g_c1[bgl*PH + p]);
                float cn = sigf(gf)*c + sigf(gi)*tanhf(gg);
                float hn = sigf(go)*tanhf(cn);
                __stcg(&g_c1n[bgl*PH + p], cn);
                __stcg(&g_h1n[bgl*PH + p], hn);
            }
        }
        barwait(mycnt, myrel, 32u);

        // ============ phase C: jrelu slice (smem) + partial logits ============
        STAGE_ISSUE(g_h1n);
        if (tid == THR-1){
            int fin = 0;
            if (step > 0){
                unsigned d;
                do {
                    asm volatile("ld.acquire.gpu.global.u32 %0,[%1];"
                                 : "=r"(d) : "l"(&g_done[step-1]) : "memory");
                } while (d < (unsigned)BB);
                fin = (__ldcg(&g_eq[step-1]) == (unsigned)BB);
            }
            smnb[1] = fin;
        }
        STAGE_WAIT();
        if (tid < 512){
            unsigned long long p1 = 0ull;
#pragma unroll 4
            for (int k4 = 0; k4 < PH/4; k4++){
                ulonglong2 h2 = hrowc[k4];
                fma2(p1, h2.x, swg2[(2*k4+0)*16 + jlc]);
                fma2(p1, h2.y, swg2[(2*k4+1)*16 + jlc]);
            }
            float lo, hi;
            unpack64(p1, lo, hi);
            float r1 = fpv + (lo + hi);
            ppartf[batc*17 + jlc] = r1 > 0.f ? r1 : 0.f;
        }
        __syncthreads();
        for (int idx = tid; idx < 32*VV; idx += THR){
            int bl_ = idx / VV, v = idx - bl_*VV;
            float s = 0.f;
#pragma unroll
            for (int j = 0; j < 16; j++)
                s = fmaf(ppartf[bl_*17 + j], wos[j*VV + v], s);
            __stcg(&g_lpart[((size_t)(b0 + bl_)*32 + sub)*32 + v], s);
        }
        barwait(mycnt, myrel, 32u);

        // ============ phase D: reduce partials + argmax + commit ============
        {
            if (wrp < 4 && lane < VV){
                const float* lp_ = &g_lpart[((size_t)myb*32 + wrp*8)*32];
                float s = 0.f;
#pragma unroll
                for (int s8 = 0; s8 < 8; s8++)
                    s += __ldcg(&lp_[s8*32 + lane]);
                sred[wrp*32 + lane] = s;
            }
            __syncthreads();
            if (wrp == 0){
                float yv = __int_as_float(0xff800000);
                if (lane < VV){
                    yv = sred[lane] + sred[32+lane] + sred[64+lane] + sred[96+lane] + b_o[lane];
                    int idx = (step*BB + myb)*VV + lane;
                    if (idx < out_size) out[idx] = yv;
                }
                float val = yv; int ix = lane;
#pragma unroll
                for (int off = 16; off > 0; off >>= 1){
                    float ov = __shfl_xor_sync(0xffffffffu, val, off);
                    int   oi = __shfl_xor_sync(0xffffffffu, ix, off);
                    if (ov > val || (ov == val && oi < ix)){ val = ov; ix = oi; }
                }
                if (lane == 0){
                    int sym = ix;
                    int fin = smnb[1];
                    int nb  = (!fin) && (sym != BLANKV);
                    int blk = (!fin) && (sym == BLANKV);
                    if (nb){
                        int olen = g_olen[myb];
                        int pos = olen < (MAXL-1) ? olen : (MAXL-1);
                        g_tok[myb*MAXL + pos] = sym;
                        g_olen[myb] = olen + 1;
                        __stcg(&g_pre[myb], sym);
                    }
                    int tm  = __ldcg(&g_time[myb]);
                    int eos = f_lens[myb] - 1;
                    if (blk){ tm = tm + 1; if (tm > eos) tm = eos; }
                    __stcg(&g_time[myb], tm);
                    if (tm == eos) atomicAdd(&g_eq[step], 1u);
                    unsigned du;
                    asm volatile("atom.add.release.gpu.global.u32 %0,[%1],1;"
                                 : "=r"(du) : "l"(&g_done[step]) : "memory");
                    smnb[0] = nb;
                }
            }
            __syncthreads();
            if (smnb[0] && tid < PH){
                int i = myb*PH + tid;
                __stcg(&g_h0[i], __ldcg(&g_h0n[i]));
                __stcg(&g_c0[i], __ldcg(&g_c0n[i]));
                __stcg(&g_h1[i], __ldcg(&g_h1n[i]));
                __stcg(&g_c1[i], __ldcg(&g_c1n[i]));
            }
        }
        barwait(mycnt, myrel, 32u);   // step boundary
    }

    // final: tokens + out_lens
    if (tid < MAXL){
        int idx = YSN + myb*MAXL + tid;
        if (idx < out_size) out[idx] = (float)g_tok[myb*MAXL + tid];
    }
    if (tid == 0){
        int idx = YSN + BB*MAXL + myb;
        if (idx < out_size) out[idx] = (float)g_olen[myb];
    }
#undef STAGE_ISSUE
#undef STAGE_WAIT
}

extern "C" void kernel_launch(void* const* d_in, const int* in_sizes, int n_in,
                              void* d_out, int out_size){
    const float* f      = (const float*)d_in[0];
    const int*   f_lens = (const int*)  d_in[1];
    const float* embed  = (const float*)d_in[2];
    const float* w_ih0  = (const float*)d_in[3];
    const float* w_hh0  = (const float*)d_in[4];
    const float* b0     = (const float*)d_in[5];
    const float* w_ih1  = (const float*)d_in[6];
    const float* w_hh1  = (const float*)d_in[7];
    const float* b1     = (const float*)d_in[8];
    const float* w_f    = (const float*)d_in[9];
    const float* w_g    = (const float*)d_in[10];
    const float* b_j    = (const float*)d_in[11];
    const float* w_o    = (const float*)d_in[12];
    const float* b_o    = (const float*)d_in[13];
    float* out = (float*)d_out;

    const int smem_bytes = 3*51200 + 20480 + SMH_F*4 + 640*16 + 16*VV*4 + 128*4 + 64;
    cudaFuncSetAttribute(decode_kernel, cudaFuncAttributeMaxDynamicSharedMemorySize, smem_bytes);

    rearr_init_kernel<<<1600, 256>>>(w_hh0, w_ih1, w_hh1, b1);
    xg0_kernel<<<VV, 256>>>(embed, w_ih0, b0);
    fproj_kernel<<<dim3(JH/64, (TT*BB)/64), 256>>>(f, w_f, b_j);
    decode_kernel<<<BB, THR, smem_bytes>>>(f_lens, w_g, w_o, b_o, out, out_size);
}

// round 16
// speedup vs baseline: 1.2837x; 1.0599x over previous
#include <cuda_runtime.h>
#include <math.h>

#define TT 200
#define BB 128
#define FH 1024
#define PH 320
#define JH 512
#define VV 29
#define BLANKV 28
#define NSTEP 400
#define MAXL 256
#define YSN (NSTEP*BB*VV)
#define THR 640

// ---------------- device scratch ----------------
__device__ float  g_Fproj[(size_t)TT*BB*JH];
__device__ float4 g_xg0[VV*PH];                // [v][p][gate]
__device__ float4 g_wA [PH*PH];                // [k][p][gate]
__device__ float4 g_wB1[PH*PH];
__device__ float4 g_wB2[PH*PH];
__device__ float4 g_b1r[PH];

__device__ float g_h0[BB*PH], g_h1[BB*PH];             // canonical committed state
__device__ float g_h0n[2][BB*PH], g_h1n[2][BB*PH];     // ping-pong candidates
__device__ float g_lpart[(size_t)BB*32*32];    // partial logits [b][sub][v(pad32)]
__device__ int g_tok[BB*MAXL];
__device__ unsigned g_eq[NSTEP];
__device__ unsigned g_done[NSTEP];
__device__ unsigned g_gcnt[4*32], g_grel[4*32];

__device__ __forceinline__ float sigf(float x){ return 1.0f/(1.0f+expf(-x)); }

__device__ __forceinline__ void barwait(unsigned* cnt, unsigned* rel, unsigned n){
    __syncthreads();
    if (threadIdx.x == 0){
        unsigned a;
        asm volatile("atom.add.release.gpu.global.u32 %0,[%1],1;"
                     : "=r"(a) : "l"(cnt) : "memory");
        a += 1u;
        if (a % n == 0u){
            asm volatile("red.release.gpu.global.max.u32 [%0],%1;"
                         :: "l"(rel), "r"(a) : "memory");
        } else {
            unsigned tgt = ((a + n - 1u)/n)*n;
            unsigned v;
            do {
                asm volatile("ld.acquire.gpu.global.u32 %0,[%1];"
                             : "=r"(v) : "l"(rel) : "memory");
            } while (v < tgt);
        }
    }
    __syncthreads();
}

__device__ __forceinline__ unsigned long long pack64(float lo, float hi){
    unsigned long long r;
    asm("mov.b64 %0,{%1,%2};" : "=l"(r) : "f"(lo), "f"(hi));
    return r;
}
__device__ __forceinline__ void unpack64(unsigned long long v, float& lo, float& hi){
    asm("mov.b64 {%0,%1},%2;" : "=f"(lo), "=f"(hi) : "l"(v));
}
__device__ __forceinline__ void fma2(unsigned long long& acc, unsigned long long a, unsigned long long b){
    asm("fma.rn.f32x2 %0,%1,%2,%0;" : "+l"(acc) : "l"(a), "l"(b));
}
__device__ __forceinline__ void add2(unsigned long long& acc, unsigned long long a){
    asm("add.rn.f32x2 %0,%0,%1;" : "+l"(acc) : "l"(a));
}
__device__ __forceinline__ void cpa16(unsigned dst, const void* src){
    asm volatile("cp.async.cg.shared.global [%0], [%1], 16;" :: "r"(dst), "l"(src));
}

// ---------------- init + weight re-layouts ----------------
__global__ void rearr_init_kernel(const float* __restrict__ w_hh0, const float* __restrict__ w_ih1,
                                  const float* __restrict__ w_hh1, const float* __restrict__ b1){
    int i = blockIdx.x*256 + threadIdx.x;
    if (i < BB*PH){ g_h0[i]=0.f; g_h1[i]=0.f; }
    if (i < BB*MAXL) g_tok[i] = BLANKV;
    if (i < NSTEP){ g_eq[i] = 0u; g_done[i] = 0u; }
    if (i < 4*32){ g_gcnt[i]=0u; g_grel[i]=0u; }
    const int Nt = PH*PH*4;
    if (i < Nt){
        int g = i & 3, p = (i >> 2) % PH, k = i / (PH*4);
        int src = k*(4*PH) + g*PH + p;
        ((float*)g_wA )[i] = w_hh0[src];
        ((float*)g_wB1)[i] = w_ih1[src];
        ((float*)g_wB2)[i] = w_hh1[src];
    }
    if (i < PH*4){
        int g = i & 3, p = i >> 2;
        ((float*)g_b1r)[i] = b1[g*PH + p];
    }
}

// ---------------- xg0 ----------------
__global__ void xg0_kernel(const float* __restrict__ embed, const float* __restrict__ w_ih0,
                           const float* __restrict__ b0v){
    __shared__ float es[PH];
    int v = blockIdx.x;
    for (int k = threadIdx.x; k < PH; k += 256) es[k] = embed[v*PH + k];
    __syncthreads();
    for (int j = threadIdx.x; j < PH*4; j += 256){
        int p = j >> 2, g = j & 3;
        float a = b0v[g*PH + p];
        const float* w = w_ih0 + g*PH + p;
        for (int k = 0; k < PH; k++) a = fmaf(es[k], w[k*(4*PH)], a);
        ((float*)g_xg0)[v*PH*4 + j] = a;
    }
}

// ---------------- Fproj ----------------
__global__ void __launch_bounds__(256) fproj_kernel(const float* __restrict__ A,
                                                    const float* __restrict__ Bm,
                                                    const float* __restrict__ bj){
    const int N = JH, K = FH;
    __shared__ float Ast[2][16][68];
    __shared__ float Bs [2][16][68];
    int bm = blockIdx.y*64, bn = blockIdx.x*64;
    int tid = threadIdx.x;
    int tx = tid & 15, ty = tid >> 4;
    int lm = tid >> 2, lkq = tid & 3;
    int lk = tid >> 4, lnq = tid & 15;

    float acc[4][4];
#pragma unroll
    for (int i = 0; i < 4; i++)
#pragma unroll
        for (int j = 0; j < 4; j++) acc[i][j] = 0.f;

    float4 va = *(const float4*)(A + (size_t)(bm+lm)*K + lkq*4);
    float4 vb = *(const float4*)(Bm + (size_t)lk*N + bn + lnq*4);
    Ast[0][lkq*4+0][lm]=va.x; Ast[0][lkq*4+1][lm]=va.y;
    Ast[0][lkq*4+2][lm]=va.z; Ast[0][lkq*4+3][lm]=va.w;
    *(float4*)&Bs[0][lk][lnq*4] = vb;
    __syncthreads();

    int buf = 0;
    for (int k0 = 16; k0 < K; k0 += 16){
        va = *(const float4*)(A + (size_t)(bm+lm)*K + k0 + lkq*4);
        vb = *(const float4*)(Bm + (size_t)(k0+lk)*N + bn + lnq*4);
#pragma unroll
        for (int k = 0; k < 16; k++){
            float4 av = *(const float4*)&Ast[buf][k][ty*4];
            float4 bv = *(const float4*)&Bs [buf][k][tx*4];
            acc[0][0]=fmaf(av.x,bv.x,acc[0][0]); acc[0][1]=fmaf(av.x,bv.y,acc[0][1]);
            acc[0][2]=fmaf(av.x,bv.z,acc[0][2]); acc[0][3]=fmaf(av.x,bv.w,acc[0][3]);
            acc[1][0]=fmaf(av.y,bv.x,acc[1][0]); acc[1][1]=fmaf(av.y,bv.y,acc[1][1]);
            acc[1][2]=fmaf(av.y,bv.z,acc[1][2]); acc[1][3]=fmaf(av.y,bv.w,acc[1][3]);
            acc[2][0]=fmaf(av.z,bv.x,acc[2][0]); acc[2][1]=fmaf(av.z,bv.y,acc[2][1]);
            acc[2][2]=fmaf(av.z,bv.z,acc[2][2]); acc[2][3]=fmaf(av.z,bv.w,acc[2][3]);
            acc[3][0]=fmaf(av.w,bv.x,acc[3][0]); acc[3][1]=fmaf(av.w,bv.y,acc[3][1]);
            acc[3][2]=fmaf(av.w,bv.z,acc[3][2]); acc[3][3]=fmaf(av.w,bv.w,acc[3][3]);
        }
        int nb = buf ^ 1;
        Ast[nb][lkq*4+0][lm]=va.x; Ast[nb][lkq*4+1][lm]=va.y;
        Ast[nb][lkq*4+2][lm]=va.z; Ast[nb][lkq*4+3][lm]=va.w;
        *(float4*)&Bs[nb][lk][lnq*4] = vb;
        __syncthreads();
        buf = nb;
    }
#pragma unroll
    for (int k = 0; k < 16; k++){
        float4 av = *(const float4*)&Ast[buf][k][ty*4];
        float4 bv = *(const float4*)&Bs [buf][k][tx*4];
        acc[0][0]=fmaf(av.x,bv.x,acc[0][0]); acc[0][1]=fmaf(av.x,bv.y,acc[0][1]);
        acc[0][2]=fmaf(av.x,bv.z,acc[0][2]); acc[0][3]=fmaf(av.x,bv.w,acc[0][3]);
        acc[1][0]=fmaf(av.y,bv.x,acc[1][0]); acc[1][1]=fmaf(av.y,bv.y,acc[1][1]);
        acc[1][2]=fmaf(av.y,bv.z,acc[1][2]); acc[1][3]=fmaf(av.y,bv.w,acc[1][3]);
        acc[2][0]=fmaf(av.z,bv.x,acc[2][0]); acc[2][1]=fmaf(av.z,bv.y,acc[2][1]);
        acc[2][2]=fmaf(av.z,bv.z,acc[2][2]); acc[2][3]=fmaf(av.z,bv.w,acc[2][3]);
        acc[3][0]=fmaf(av.w,bv.x,acc[3][0]); acc[3][1]=fmaf(av.w,bv.y,acc[3][1]);
        acc[3][2]=fmaf(av.w,bv.z,acc[3][2]); acc[3][3]=fmaf(av.w,bv.w,acc[3][3]);
    }
#pragma unroll
    for (int i = 0; i < 4; i++)
#pragma unroll
        for (int j = 0; j < 4; j++){
            int n = bn + tx*4 + j;
            g_Fproj[(size_t)(bm + ty*4 + i)*N + n] = acc[i][j] + bj[n];
        }
}

// ================= persistent decode: 128 CTAs x 640 threads =================
#define SW_U2  3200
#define HSTR   324
#define SMH_F  (32*HSTR)

__global__ void __launch_bounds__(THR,1)
decode_kernel(const int* __restrict__ f_lens, const float* __restrict__ w_g,
              const float* __restrict__ w_o, const float* __restrict__ b_o,
              float* __restrict__ out, int out_size){
    extern __shared__ float smem[];
    ulonglong2* swA2  = (ulonglong2*)smem;
    ulonglong2* swB12 = swA2  + SW_U2;
    ulonglong2* swB22 = swB12 + SW_U2;
    unsigned long long* swg2 = (unsigned long long*)(swB22 + SW_U2);  // [160 k2][16 j]
    float*  smh   = (float*)(swg2 + 160*16);
    ulonglong2* ppart = (ulonglong2*)(smh + SMH_F);   // LSTM k-split partials
    float*  ppartf = (float*)ppart;                   // ALIAS: phase-C jrelu slice [32][17]
    float*  wos   = (float*)(ppart + 640);            // w_o slice [16 j][29 v]
    int*    snb   = (int*)(wos + 16*VV);              // per-batch decode state (group)
    int*    spre  = snb + 32;
    int*    stime = spre + 32;
    int*    solen = stime + 32;
    int*    seos  = solen + 32;
    float*  sbo   = (float*)(seos + 32);              // b_o copy [32]
    int*    smnb  = (int*)(sbo + 32);                 // [1]=fin

    const int tid = threadIdx.x;
    const int cta = blockIdx.x;
    const int bb  = cta >> 5;
    const int sub = cta & 31;
    const int b0  = bb*32;
    const int lane = tid & 31, wrp = tid >> 5;   // 0..19
    const int khalf = (tid >= 320);
    const int tidp  = khalf ? tid - 320 : tid;
    const int wrpp  = tidp >> 5;
    const int psel = lane & 1, bl4 = lane >> 1;
    const int bhalf = (wrpp < 5) ? 0 : 1, pduo = (wrpp < 5) ? wrpp : wrpp - 5;
    const int bat = bhalf*16 + bl4;
    const int lp  = pduo*2 + psel;
    const int p   = sub*10 + lp;
    const int bgl = b0 + bat;
    // phase C remap: 16 active warps, warp covers 2 j x 16 batches
    const int jlc  = (wrp >> 1)*2 + (lane & 1);
    const int batc = (wrp & 1)*16 + (lane >> 1);
    const int myb = cta;

    const unsigned smh_u32 = (unsigned)__cvta_generic_to_shared(smh);

    unsigned* mycnt = &g_gcnt[bb*32];
    unsigned* myrel = &g_grel[bb*32];

    // ---- one-time weight preload ----
    for (int i = tid; i < 1600; i += THR){
        int k2 = i/10, q = i - k2*10;
        int s0 = (2*k2)*PH + sub*10 + q, s1 = (2*k2+1)*PH + sub*10 + q;
        float4 a = g_wA[s0],  b = g_wA[s1];
        swA2[i*2+0] = make_ulonglong2(pack64(a.x,b.x), pack64(a.y,b.y));
        swA2[i*2+1] = make_ulonglong2(pack64(a.z,b.z), pack64(a.w,b.w));
        a = g_wB1[s0]; b = g_wB1[s1];
        swB12[i*2+0] = make_ulonglong2(pack64(a.x,b.x), pack64(a.y,b.y));
        swB12[i*2+1] = make_ulonglong2(pack64(a.z,b.z), pack64(a.w,b.w));
        a = g_wB2[s0]; b = g_wB2[s1];
        swB22[i*2+0] = make_ulonglong2(pack64(a.x,b.x), pack64(a.y,b.y));
        swB22[i*2+1] = make_ulonglong2(pack64(a.z,b.z), pack64(a.w,b.w));
    }
    for (int i = tid; i < 160*16; i += THR){
        int k2 = i >> 4, j = i & 15;
        swg2[i] = pack64(w_g[(size_t)(2*k2)*JH + sub*16 + j],
                         w_g[(size_t)(2*k2+1)*JH + sub*16 + j]);
    }
    for (int i = tid; i < 16*VV; i += THR){
        int j = i / VV, v = i - j*VV;
        wos[i] = w_o[(size_t)(sub*16 + j)*VV + v];
    }
    if (tid < 32){
        snb[tid]=0; spre[tid]=0; stime[tid]=0; solen[tid]=0;
        seos[tid] = f_lens[b0 + tid] - 1;
        sbo[tid] = (tid < VV) ? b_o[tid] : 0.f;
    }
    __syncthreads();

    const ulonglong2* hrow2 = (const ulonglong2*)(smh + bat*HSTR);
    const ulonglong2* hrowc = (const ulonglong2*)(smh + batc*HSTR);
    const int k4beg = khalf*40, k4end = khalf*40 + 40;

    // c-state lives in registers (thread owns fixed (bat,p) forever)
    float c0r = 0.f, c1r = 0.f, c0nr = 0.f, c1nr = 0.f;

#define STAGE_SEL(CAN, PING) do{                                               \
        for (int e = tid; e < 2560; e += THR){                                 \
            int j_ = e/80, q_ = e - j_*80;                                     \
            const float* src = snb[j_] ? &(PING)[(size_t)(b0+j_)*PH + q_*4]    \
                                       : &(CAN)[(size_t)(b0+j_)*PH + q_*4];    \
            cpa16(smh_u32 + (unsigned)(j_*HSTR + q_*4)*4u, src);               \
        }                                                                      \
        asm volatile("cp.async.commit_group;" ::: "memory"); } while(0)
#define STAGE(SRC) do{                                                         \
        for (int e = tid; e < 2560; e += THR){                                 \
            int j_ = e/80, q_ = e - j_*80;                                     \
            cpa16(smh_u32 + (unsigned)(j_*HSTR + q_*4)*4u,                     \
                  &(SRC)[(size_t)(b0+j_)*PH + q_*4]);                          \
        }                                                                      \
        asm volatile("cp.async.commit_group;" ::: "memory"); } while(0)
#define STAGE_WAIT() do{ asm volatile("cp.async.wait_group 0;" ::: "memory"); \
                         __syncthreads(); } while(0)

    for (int step = 0; step < NSTEP; step++){
        const int cur = step & 1, prv = cur ^ 1;
        const float* h0n_prv = g_h0n[prv];
        const float* h1n_prv = g_h1n[prv];
        float* h0n_cur = g_h0n[cur];
        float* h1n_cur = g_h1n[cur];

        // ============ phase A: LSTM0 ============
        STAGE_SEL(g_h0, h0n_prv);
        // c-reg commit using last step's nb (snb persists from D)
        if (!khalf && snb[bat]){ c0r = c0nr; c1r = c1nr; }
        // distributed h0 write-back (idempotent; stagers with snb=1 don't read g_h0)
        if (tid < 320){
            int b_ = tid/10, pp_ = sub*10 + tid - (tid/10)*10;
            if (snb[b_]) __stcg(&g_h0[(b0+b_)*PH + pp_], __ldcg(&h0n_prv[(b0+b_)*PH + pp_]));
        }
        // hoisted prefixes
        unsigned long long a0 = 0ull, a1 = 0ull, a2 = 0ull, a3 = 0ull;
        if (!khalf){
            int pre = spre[bat];
            float4 x0 = g_xg0[pre*PH + p];
            a0 = pack64(x0.x,0.f); a1 = pack64(x0.y,0.f);
            a2 = pack64(x0.z,0.f); a3 = pack64(x0.w,0.f);
        }
        float fpv = 0.f;
        if (tid < 512){
            int t = stime[batc];
            fpv = __ldcg(&g_Fproj[((size_t)t*BB + b0 + batc)*JH + sub*16 + jlc]);
        }
        STAGE_WAIT();
        {
#pragma unroll 4
            for (int k4 = k4beg; k4 < k4end; k4++){
                ulonglong2 h2 = hrow2[k4];
                int base = k4*40 + lp*2;
                ulonglong2 wa0 = swA2[base+0];
                ulonglong2 wa1 = swA2[base+1];
                ulonglong2 wb0 = swA2[base+20];
                ulonglong2 wb1 = swA2[base+21];
                fma2(a0,h2.x,wa0.x); fma2(a1,h2.x,wa0.y); fma2(a2,h2.x,wa1.x); fma2(a3,h2.x,wa1.y);
                fma2(a0,h2.y,wb0.x); fma2(a1,h2.y,wb0.y); fma2(a2,h2.y,wb1.x); fma2(a3,h2.y,wb1.y);
            }
            if (khalf){
                ppart[tidp*2+0] = make_ulonglong2(a0, a1);
                ppart[tidp*2+1] = make_ulonglong2(a2, a3);
            }
            __syncthreads();           // smh readers done; ppart visible
            STAGE_SEL(g_h1, h1n_prv);  // overlap h1 stage with A tail
            // distributed h1 write-back
            if (tid < 320){
                int b_ = tid/10, pp_ = sub*10 + tid - (tid/10)*10;
                if (snb[b_]) __stcg(&g_h1[(b0+b_)*PH + pp_], __ldcg(&h1n_prv[(b0+b_)*PH + pp_]));
            }
            if (!khalf){
                ulonglong2 q0 = ppart[tidp*2+0], q1 = ppart[tidp*2+1];
                add2(a0, q0.x); add2(a1, q0.y); add2(a2, q1.x); add2(a3, q1.y);
                float l0,h0v,l1,h1v,l2,h2v,l3,h3v;
                unpack64(a0,l0,h0v); unpack64(a1,l1,h1v); unpack64(a2,l2,h2v); unpack64(a3,l3,h3v);
                float gi=l0+h0v, gf=l1+h1v, gg=l2+h2v, go=l3+h3v;
                float cn = sigf(gf)*c0r + sigf(gi)*tanhf(gg);
                float hn = sigf(go)*tanhf(cn);
                c0nr = cn;
                __stcg(&h0n_cur[bgl*PH + p], hn);
            }
        }

        // ============ phase B: LSTM1 (pass0 on old h1) ============
        {
            if (!khalf){
                float4 bv = g_b1r[p];
                a0 = pack64(bv.x,0.f); a1 = pack64(bv.y,0.f);
                a2 = pack64(bv.z,0.f); a3 = pack64(bv.w,0.f);
            } else { a0 = a1 = a2 = a3 = 0ull; }

            STAGE_WAIT();   // h1 ready
#pragma unroll 4
            for (int k4 = k4beg; k4 < k4end; k4++){
                ulonglong2 h2 = hrow2[k4];
                int base = k4*40 + lp*2;
                ulonglong2 wa0 = swB22[base+0];
                ulonglong2 wa1 = swB22[base+1];
                ulonglong2 wb0 = swB22[base+20];
                ulonglong2 wb1 = swB22[base+21];
                fma2(a0,h2.x,wa0.x); fma2(a1,h2.x,wa0.y); fma2(a2,h2.x,wa1.x); fma2(a3,h2.x,wa1.y);
                fma2(a0,h2.y,wb0.x); fma2(a1,h2.y,wb0.y); fma2(a2,h2.y,wb1.x); fma2(a3,h2.y,wb1.y);
            }

            barwait(mycnt, myrel, 32u);   // barrier 1: A outputs complete

            STAGE(h0n_cur);
            STAGE_WAIT();
#pragma unroll 4
            for (int k4 = k4beg; k4 < k4end; k4++){
                ulonglong2 h2 = hrow2[k4];
                int base = k4*40 + lp*2;
                ulonglong2 wa0 = swB12[base+0];
                ulonglong2 wa1 = swB12[base+1];
                ulonglong2 wb0 = swB12[base+20];
                ulonglong2 wb1 = swB12[base+21];
                fma2(a0,h2.x,wa0.x); fma2(a1,h2.x,wa0.y); fma2(a2,h2.x,wa1.x); fma2(a3,h2.x,wa1.y);
                fma2(a0,h2.y,wb0.x); fma2(a1,h2.y,wb0.y); fma2(a2,h2.y,wb1.x); fma2(a3,h2.y,wb1.y);
            }
            if (khalf){
                ppart[tidp*2+0] = make_ulonglong2(a0, a1);
                ppart[tidp*2+1] = make_ulonglong2(a2, a3);
            }
            __syncthreads();
            if (!khalf){
                ulonglong2 q0 = ppart[tidp*2+0], q1 = ppart[tidp*2+1];
                add2(a0, q0.x); add2(a1, q0.y); add2(a2, q1.x); add2(a3, q1.y);
                float l0,h0v,l1,h1v,l2,h2v,l3,h3v;
                unpack64(a0,l0,h0v); unpack64(a1,l1,h1v); unpack64(a2,l2,h2v); unpack64(a3,l3,h3v);
                float gi=l0+h0v, gf=l1+h1v, gg=l2+h2v, go=l3+h3v;
                float cn = sigf(gf)*c1r + sigf(gi)*tanhf(gg);
                float hn = sigf(go)*tanhf(cn);
                c1nr = cn;
                __stcg(&h1n_cur[bgl*PH + p], hn);
            }
        }
        barwait(mycnt, myrel, 32u);       // barrier 2: B outputs complete

        // ============ phase C: jrelu slice (smem) + partial logits ============
        STAGE(h1n_cur);
        if (tid == THR-1){
            int fin = 0;
            if (step > 0){
                unsigned d;
                do {
                    asm volatile("ld.acquire.gpu.global.u32 %0,[%1];"
                                 : "=r"(d) : "l"(&g_done[step-1]) : "memory");
                } while (d < (unsigned)BB);
                fin = (__ldcg(&g_eq[step-1]) == (unsigned)BB);
            }
            smnb[1] = fin;
        }
        STAGE_WAIT();
        if (tid < 512){
            unsigned long long p1 = 0ull;
#pragma unroll 4
            for (int k4 = 0; k4 < PH/4; k4++){
                ulonglong2 h2 = hrowc[k4];
                fma2(p1, h2.x, swg2[(2*k4+0)*16 + jlc]);
                fma2(p1, h2.y, swg2[(2*k4+1)*16 + jlc]);
            }
            float lo, hi;
            unpack64(p1, lo, hi);
            float r1 = fpv + (lo + hi);
            ppartf[batc*17 + jlc] = r1 > 0.f ? r1 : 0.f;
        }
        __syncthreads();
        for (int idx = tid; idx < 32*VV; idx += THR){
            int bl_ = idx / VV, v = idx - bl_*VV;
            float s = 0.f;
#pragma unroll
            for (int j = 0; j < 16; j++)
                s = fmaf(ppartf[bl_*17 + j], wos[j*VV + v], s);
            __stcg(&g_lpart[((size_t)(b0 + bl_)*32 + sub)*32 + v], s);
        }
        barwait(mycnt, myrel, 32u);       // barrier 3: lpart complete

        // ============ phase D: REDUNDANT reduce+argmax (all 32 batches per CTA) ============
        if (wrp < 16){
#pragma unroll
            for (int bi = 0; bi < 2; bi++){
                int bq = wrp*2 + bi;
                float s = __int_as_float(0xff800000);
                if (lane < VV){
                    s = sbo[lane];
                    const float* lq = &g_lpart[((size_t)(b0+bq)*32)*32 + lane];
#pragma unroll 8
                    for (int sb = 0; sb < 32; sb++)
                        s += __ldcg(&lq[sb*32]);
                    if (bq == sub){
                        int idx = (step*BB + myb)*VV + lane;
                        if (idx < out_size) out[idx] = s;
                    }
                }
                float val = s; int ix = lane;
#pragma unroll
                for (int off = 16; off > 0; off >>= 1){
                    float ov = __shfl_xor_sync(0xffffffffu, val, off);
                    int   oi = __shfl_xor_sync(0xffffffffu, ix, off);
                    if (ov > val || (ov == val && oi < ix)){ val = ov; ix = oi; }
                }
                if (lane == 0){
                    int sym = ix;
                    int fin = smnb[1];
                    int nb  = (!fin) && (sym != BLANKV);
                    int blk = (!fin) && (sym == BLANKV);
                    snb[bq] = nb;
                    if (nb){
                        int olen = solen[bq];
                        int pos = olen < (MAXL-1) ? olen : (MAXL-1);
                        if (bq == sub) g_tok[myb*MAXL + pos] = sym;
                        solen[bq] = olen + 1;
                        spre[bq] = sym;
                    }
                    int tm  = stime[bq];
                    int eos = seos[bq];
                    if (blk){ tm = tm + 1; if (tm > eos) tm = eos; }
                    stime[bq] = tm;
                    if (bq == sub){
                        if (tm == eos) atomicAdd(&g_eq[step], 1u);
                        unsigned du;
                        asm volatile("atom.add.release.gpu.global.u32 %0,[%1],1;"
                                     : "=r"(du) : "l"(&g_done[step]) : "memory");
                    }
                }
            }
        }
        __syncthreads();   // local only: snb/spre/stime visible for next A
    }

    // final: tokens + out_lens
    if (tid < MAXL){
        int idx = YSN + myb*MAXL + tid;
        if (idx < out_size) out[idx] = (float)g_tok[myb*MAXL + tid];
    }
    if (tid == 0){
        int idx = YSN + BB*MAXL + myb;
        if (idx < out_size) out[idx] = (float)solen[sub];
    }
#undef STAGE_SEL
#undef STAGE
#undef STAGE_WAIT
}

extern "C" void kernel_launch(void* const* d_in, const int* in_sizes, int n_in,
                              void* d_out, int out_size){
    const float* f      = (const float*)d_in[0];
    const int*   f_lens = (const int*)  d_in[1];
    const float* embed  = (const float*)d_in[2];
    const float* w_ih0  = (const float*)d_in[3];
    const float* w_hh0  = (const float*)d_in[4];
    const float* b0     = (const float*)d_in[5];
    const float* w_ih1  = (const float*)d_in[6];
    const float* w_hh1  = (const float*)d_in[7];
    const float* b1     = (const float*)d_in[8];
    const float* w_f    = (const float*)d_in[9];
    const float* w_g    = (const float*)d_in[10];
    const float* b_j    = (const float*)d_in[11];
    const float* w_o    = (const float*)d_in[12];
    const float* b_o    = (const float*)d_in[13];
    float* out = (float*)d_out;

    // 153600 + 20480 + 41472 + 10240 + 1856 + 5*128 + 128 + 8 ≈ 228,480 B
    const int smem_bytes = 3*51200 + 20480 + SMH_F*4 + 640*16 + 16*VV*4 + 6*32*4 + 64;
    cudaFuncSetAttribute(decode_kernel, cudaFuncAttributeMaxDynamicSharedMemorySize, smem_bytes);

    rearr_init_kernel<<<1600, 256>>>(w_hh0, w_ih1, w_hh1, b1);
    xg0_kernel<<<VV, 256>>>(embed, w_ih0, b0);
    fproj_kernel<<<dim3(JH/64, (TT*BB)/64), 256>>>(f, w_f, b_j);
    decode_kernel<<<BB, THR, smem_bytes>>>(f_lens, w_g, w_o, b_o, out, out_size);
}

// round 17
// speedup vs baseline: 1.2957x; 1.0093x over previous
#include <cuda_runtime.h>
#include <math.h>

#define TT 200
#define BB 128
#define FH 1024
#define PH 320
#define JH 512
#define VV 29
#define BLANKV 28
#define NSTEP 400
#define MAXL 256
#define YSN (NSTEP*BB*VV)
#define THR 640

// ---------------- device scratch ----------------
__device__ float  g_Fproj[(size_t)TT*BB*JH];
__device__ float4 g_xg0[VV*PH];                // [v][p][gate]
__device__ float4 g_wA [PH*PH];                // [k][p][gate]
__device__ float4 g_wB1[PH*PH];
__device__ float4 g_wB2[PH*PH];
__device__ float4 g_b1r[PH];

__device__ float g_h0[BB*PH], g_h1[BB*PH];             // canonical committed state
__device__ float g_h0n[2][BB*PH], g_h1n[2][BB*PH];     // ping-pong candidates
__device__ float g_lpart[(size_t)BB*32*32];    // partial logits [b][sub][v(pad32)]
__device__ int g_tok[BB*MAXL];
__device__ unsigned g_eq[NSTEP];
__device__ unsigned g_done[NSTEP];
__device__ unsigned g_gcnt[4*32], g_grel[4*32];

__device__ __forceinline__ float sigf(float x){ return 1.0f/(1.0f+expf(-x)); }

__device__ __forceinline__ void barwait(unsigned* cnt, unsigned* rel, unsigned n){
    __syncthreads();
    if (threadIdx.x == 0){
        unsigned a;
        asm volatile("atom.add.release.gpu.global.u32 %0,[%1],1;"
                     : "=r"(a) : "l"(cnt) : "memory");
        a += 1u;
        if (a % n == 0u){
            asm volatile("red.release.gpu.global.max.u32 [%0],%1;"
                         :: "l"(rel), "r"(a) : "memory");
        } else {
            unsigned tgt = ((a + n - 1u)/n)*n;
            unsigned v;
            do {
                asm volatile("ld.acquire.gpu.global.u32 %0,[%1];"
                             : "=r"(v) : "l"(rel) : "memory");
            } while (v < tgt);
        }
    }
    __syncthreads();
}

__device__ __forceinline__ unsigned long long pack64(float lo, float hi){
    unsigned long long r;
    asm("mov.b64 %0,{%1,%2};" : "=l"(r) : "f"(lo), "f"(hi));
    return r;
}
__device__ __forceinline__ void unpack64(unsigned long long v, float& lo, float& hi){
    asm("mov.b64 {%0,%1},%2;" : "=f"(lo), "=f"(hi) : "l"(v));
}
__device__ __forceinline__ unsigned long long dup2(float h){
    unsigned long long r;
    asm("mov.b64 %0,{%1,%1};" : "=l"(r) : "f"(h));
    return r;
}
__device__ __forceinline__ void fma2(unsigned long long& acc, unsigned long long a, unsigned long long b){
    asm("fma.rn.f32x2 %0,%1,%2,%0;" : "+l"(acc) : "l"(a), "l"(b));
}
__device__ __forceinline__ void add2(unsigned long long& acc, unsigned long long a){
    asm("add.rn.f32x2 %0,%0,%1;" : "+l"(acc) : "l"(a));
}
__device__ __forceinline__ void cpa16(unsigned dst, const void* src){
    asm volatile("cp.async.cg.shared.global [%0], [%1], 16;" :: "r"(dst), "l"(src));
}

// ---------------- init + weight re-layouts ----------------
__global__ void rearr_init_kernel(const float* __restrict__ w_hh0, const float* __restrict__ w_ih1,
                                  const float* __restrict__ w_hh1, const float* __restrict__ b1){
    int i = blockIdx.x*256 + threadIdx.x;
    if (i < BB*PH){ g_h0[i]=0.f; g_h1[i]=0.f; }
    if (i < BB*MAXL) g_tok[i] = BLANKV;
    if (i < NSTEP){ g_eq[i] = 0u; g_done[i] = 0u; }
    if (i < 4*32){ g_gcnt[i]=0u; g_grel[i]=0u; }
    const int Nt = PH*PH*4;
    if (i < Nt){
        int g = i & 3, p = (i >> 2) % PH, k = i / (PH*4);
        int src = k*(4*PH) + g*PH + p;
        ((float*)g_wA )[i] = w_hh0[src];
        ((float*)g_wB1)[i] = w_ih1[src];
        ((float*)g_wB2)[i] = w_hh1[src];
    }
    if (i < PH*4){
        int g = i & 3, p = i >> 2;
        ((float*)g_b1r)[i] = b1[g*PH + p];
    }
}

// ---------------- xg0 ----------------
__global__ void xg0_kernel(const float* __restrict__ embed, const float* __restrict__ w_ih0,
                           const float* __restrict__ b0v){
    __shared__ float es[PH];
    int v = blockIdx.x;
    for (int k = threadIdx.x; k < PH; k += 256) es[k] = embed[v*PH + k];
    __syncthreads();
    for (int j = threadIdx.x; j < PH*4; j += 256){
        int p = j >> 2, g = j & 3;
        float a = b0v[g*PH + p];
        const float* w = w_ih0 + g*PH + p;
        for (int k = 0; k < PH; k++) a = fmaf(es[k], w[k*(4*PH)], a);
        ((float*)g_xg0)[v*PH*4 + j] = a;
    }
}

// ---------------- Fproj: 128x64 tiles, f32x2 math, double-buffered ----------------
__global__ void __launch_bounds__(256) fproj_kernel(const float* __restrict__ A,
                                                    const float* __restrict__ Bm,
                                                    const float* __restrict__ bj){
    const int N = JH, K = FH;
    __shared__ float Ast[2][16][132];   // [k][m], m=128 (+4 pad)
    __shared__ float Bs [2][16][68];    // [k][n], n=64 (+4 pad)
    const int bm = blockIdx.y*128, bn = blockIdx.x*64;
    const int tid = threadIdx.x;
    const int tx = tid & 15, ty = tid >> 4;     // n-quad, m-oct
    const int lkB = tid >> 4, lnqB = tid & 15;  // B loader

    unsigned long long acc[4][4];               // [m-pair][n]
#pragma unroll
    for (int i = 0; i < 4; i++)
#pragma unroll
        for (int j = 0; j < 4; j++) acc[i][j] = 0ull;

    // prologue: tile 0
    {
        int r0 = tid >> 2,        q0 = tid & 3;
        int r1 = (tid+256) >> 2,  q1 = (tid+256) & 3;
        float4 va0 = *(const float4*)(A + (size_t)(bm+r0)*K + q0*4);
        float4 va1 = *(const float4*)(A + (size_t)(bm+r1)*K + q1*4);
        float4 vb  = *(const float4*)(Bm + (size_t)lkB*N + bn + lnqB*4);
        Ast[0][q0*4+0][r0]=va0.x; Ast[0][q0*4+1][r0]=va0.y;
        Ast[0][q0*4+2][r0]=va0.z; Ast[0][q0*4+3][r0]=va0.w;
        Ast[0][q1*4+0][r1]=va1.x; Ast[0][q1*4+1][r1]=va1.y;
        Ast[0][q1*4+2][r1]=va1.z; Ast[0][q1*4+3][r1]=va1.w;
        *(float4*)&Bs[0][lkB][lnqB*4] = vb;
    }
    __syncthreads();

    int buf = 0;
    for (int k0 = 16; k0 < K; k0 += 16){
        // prefetch next tile into regs
        int r0 = tid >> 2,        q0 = tid & 3;
        int r1 = (tid+256) >> 2,  q1 = (tid+256) & 3;
        float4 va0 = *(const float4*)(A + (size_t)(bm+r0)*K + k0 + q0*4);
        float4 va1 = *(const float4*)(A + (size_t)(bm+r1)*K + k0 + q1*4);
        float4 vb  = *(const float4*)(Bm + (size_t)(k0+lkB)*N + bn + lnqB*4);
#pragma unroll
        for (int k = 0; k < 16; k++){
            ulonglong2 am01 = *(const ulonglong2*)&Ast[buf][k][ty*8];
            ulonglong2 am23 = *(const ulonglong2*)&Ast[buf][k][ty*8+4];
            float4 bv = *(const float4*)&Bs[buf][k][tx*4];
            unsigned long long h0 = dup2(bv.x), h1 = dup2(bv.y);
            unsigned long long h2 = dup2(bv.z), h3 = dup2(bv.w);
            fma2(acc[0][0], am01.x, h0); fma2(acc[0][1], am01.x, h1);
            fma2(acc[0][2], am01.x, h2); fma2(acc[0][3], am01.x, h3);
            fma2(acc[1][0], am01.y, h0); fma2(acc[1][1], am01.y, h1);
            fma2(acc[1][2], am01.y, h2); fma2(acc[1][3], am01.y, h3);
            fma2(acc[2][0], am23.x, h0); fma2(acc[2][1], am23.x, h1);
            fma2(acc[2][2], am23.x, h2); fma2(acc[2][3], am23.x, h3);
            fma2(acc[3][0], am23.y, h0); fma2(acc[3][1], am23.y, h1);
            fma2(acc[3][2], am23.y, h2); fma2(acc[3][3], am23.y, h3);
        }
        int nb = buf ^ 1;
        Ast[nb][q0*4+0][r0]=va0.x; Ast[nb][q0*4+1][r0]=va0.y;
        Ast[nb][q0*4+2][r0]=va0.z; Ast[nb][q0*4+3][r0]=va0.w;
        Ast[nb][q1*4+0][r1]=va1.x; Ast[nb][q1*4+1][r1]=va1.y;
        Ast[nb][q1*4+2][r1]=va1.z; Ast[nb][q1*4+3][r1]=va1.w;
        *(float4*)&Bs[nb][lkB][lnqB*4] = vb;
        __syncthreads();
        buf = nb;
    }
#pragma unroll
    for (int k = 0; k < 16; k++){
        ulonglong2 am01 = *(const ulonglong2*)&Ast[buf][k][ty*8];
        ulonglong2 am23 = *(const ulonglong2*)&Ast[buf][k][ty*8+4];
        float4 bv = *(const float4*)&Bs[buf][k][tx*4];
        unsigned long long h0 = dup2(bv.x), h1 = dup2(bv.y);
        unsigned long long h2 = dup2(bv.z), h3 = dup2(bv.w);
        fma2(acc[0][0], am01.x, h0); fma2(acc[0][1], am01.x, h1);
        fma2(acc[0][2], am01.x, h2); fma2(acc[0][3], am01.x, h3);
        fma2(acc[1][0], am01.y, h0); fma2(acc[1][1], am01.y, h1);
        fma2(acc[1][2], am01.y, h2); fma2(acc[1][3], am01.y, h3);
        fma2(acc[2][0], am23.x, h0); fma2(acc[2][1], am23.x, h1);
        fma2(acc[2][2], am23.x, h2); fma2(acc[2][3], am23.x, h3);
        fma2(acc[3][0], am23.y, h0); fma2(acc[3][1], am23.y, h1);
        fma2(acc[3][2], am23.y, h2); fma2(acc[3][3], am23.y, h3);
    }
    // epilogue: acc[mp][j] holds rows (ty*8+2*mp, ty*8+2*mp+1), col tx*4+j
#pragma unroll
    for (int mp = 0; mp < 4; mp++){
#pragma unroll
        for (int j = 0; j < 4; j++){
            float lo, hi;
            unpack64(acc[mp][j], lo, hi);
            int m = bm + ty*8 + mp*2;
            int n = bn + tx*4 + j;
            float b = bj[n];
            g_Fproj[(size_t)m*N + n]     = lo + b;
            g_Fproj[(size_t)(m+1)*N + n] = hi + b;
        }
    }
}

// ================= persistent decode: 128 CTAs x 640 threads (R15 winner, unchanged) =================
#define SW_U2  3200
#define HSTR   324
#define SMH_F  (32*HSTR)

__global__ void __launch_bounds__(THR,1)
decode_kernel(const int* __restrict__ f_lens, const float* __restrict__ w_g,
              const float* __restrict__ w_o, const float* __restrict__ b_o,
              float* __restrict__ out, int out_size){
    extern __shared__ float smem[];
    ulonglong2* swA2  = (ulonglong2*)smem;
    ulonglong2* swB12 = swA2  + SW_U2;
    ulonglong2* swB22 = swB12 + SW_U2;
    unsigned long long* swg2 = (unsigned long long*)(swB22 + SW_U2);  // [160 k2][16 j]
    float*  smh   = (float*)(swg2 + 160*16);
    ulonglong2* ppart = (ulonglong2*)(smh + SMH_F);   // LSTM k-split partials
    float*  ppartf = (float*)ppart;                   // ALIAS: phase-C jrelu slice [32][17]
    float*  wos   = (float*)(ppart + 640);            // w_o slice [16 j][29 v]
    int*    snb   = (int*)(wos + 16*VV);              // per-batch decode state (group)
    int*    spre  = snb + 32;
    int*    stime = spre + 32;
    int*    solen = stime + 32;
    int*    seos  = solen + 32;
    float*  sbo   = (float*)(seos + 32);              // b_o copy [32]
    int*    smnb  = (int*)(sbo + 32);                 // [1]=fin

    const int tid = threadIdx.x;
    const int cta = blockIdx.x;
    const int bb  = cta >> 5;
    const int sub = cta & 31;
    const int b0  = bb*32;
    const int lane = tid & 31, wrp = tid >> 5;   // 0..19
    const int khalf = (tid >= 320);
    const int tidp  = khalf ? tid - 320 : tid;
    const int wrpp  = tidp >> 5;
    const int psel = lane & 1, bl4 = lane >> 1;
    const int bhalf = (wrpp < 5) ? 0 : 1, pduo = (wrpp < 5) ? wrpp : wrpp - 5;
    const int bat = bhalf*16 + bl4;
    const int lp  = pduo*2 + psel;
    const int p   = sub*10 + lp;
    const int bgl = b0 + bat;
    const int jlc  = (wrp >> 1)*2 + (lane & 1);
    const int batc = (wrp & 1)*16 + (lane >> 1);
    const int myb = cta;

    const unsigned smh_u32 = (unsigned)__cvta_generic_to_shared(smh);

    unsigned* mycnt = &g_gcnt[bb*32];
    unsigned* myrel = &g_grel[bb*32];

    // ---- one-time weight preload ----
    for (int i = tid; i < 1600; i += THR){
        int k2 = i/10, q = i - k2*10;
        int s0 = (2*k2)*PH + sub*10 + q, s1 = (2*k2+1)*PH + sub*10 + q;
        float4 a = g_wA[s0],  b = g_wA[s1];
        swA2[i*2+0] = make_ulonglong2(pack64(a.x,b.x), pack64(a.y,b.y));
        swA2[i*2+1] = make_ulonglong2(pack64(a.z,b.z), pack64(a.w,b.w));
        a = g_wB1[s0]; b = g_wB1[s1];
        swB12[i*2+0] = make_ulonglong2(pack64(a.x,b.x), pack64(a.y,b.y));
        swB12[i*2+1] = make_ulonglong2(pack64(a.z,b.z), pack64(a.w,b.w));
        a = g_wB2[s0]; b = g_wB2[s1];
        swB22[i*2+0] = make_ulonglong2(pack64(a.x,b.x), pack64(a.y,b.y));
        swB22[i*2+1] = make_ulonglong2(pack64(a.z,b.z), pack64(a.w,b.w));
    }
    for (int i = tid; i < 160*16; i += THR){
        int k2 = i >> 4, j = i & 15;
        swg2[i] = pack64(w_g[(size_t)(2*k2)*JH + sub*16 + j],
                         w_g[(size_t)(2*k2+1)*JH + sub*16 + j]);
    }
    for (int i = tid; i < 16*VV; i += THR){
        int j = i / VV, v = i - j*VV;
        wos[i] = w_o[(size_t)(sub*16 + j)*VV + v];
    }
    if (tid < 32){
        snb[tid]=0; spre[tid]=0; stime[tid]=0; solen[tid]=0;
        seos[tid] = f_lens[b0 + tid] - 1;
        sbo[tid] = (tid < VV) ? b_o[tid] : 0.f;
    }
    __syncthreads();

    const ulonglong2* hrow2 = (const ulonglong2*)(smh + bat*HSTR);
    const ulonglong2* hrowc = (const ulonglong2*)(smh + batc*HSTR);
    const int k4beg = khalf*40, k4end = khalf*40 + 40;

    float c0r = 0.f, c1r = 0.f, c0nr = 0.f, c1nr = 0.f;

#define STAGE_SEL(CAN, PING) do{                                               \
        for (int e = tid; e < 2560; e += THR){                                 \
            int j_ = e/80, q_ = e - j_*80;                                     \
            const float* src = snb[j_] ? &(PING)[(size_t)(b0+j_)*PH + q_*4]    \
                                       : &(CAN)[(size_t)(b0+j_)*PH + q_*4];    \
            cpa16(smh_u32 + (unsigned)(j_*HSTR + q_*4)*4u, src);               \
        }                                                                      \
        asm volatile("cp.async.commit_group;" ::: "memory"); } while(0)
#define STAGE(SRC) do{                                                         \
        for (int e = tid; e < 2560; e += THR){                                 \
            int j_ = e/80, q_ = e - j_*80;                                     \
            cpa16(smh_u32 + (unsigned)(j_*HSTR + q_*4)*4u,                     \
                  &(SRC)[(size_t)(b0+j_)*PH + q_*4]);                          \
        }                                                                      \
        asm volatile("cp.async.commit_group;" ::: "memory"); } while(0)
#define STAGE_WAIT() do{ asm volatile("cp.async.wait_group 0;" ::: "memory"); \
                         __syncthreads(); } while(0)

    for (int step = 0; step < NSTEP; step++){
        const int cur = step & 1, prv = cur ^ 1;
        const float* h0n_prv = g_h0n[prv];
        const float* h1n_prv = g_h1n[prv];
        float* h0n_cur = g_h0n[cur];
        float* h1n_cur = g_h1n[cur];

        // ============ phase A: LSTM0 ============
        STAGE_SEL(g_h0, h0n_prv);
        if (!khalf && snb[bat]){ c0r = c0nr; c1r = c1nr; }
        if (tid < 320){
            int b_ = tid/10, pp_ = sub*10 + tid - (tid/10)*10;
            if (snb[b_]) __stcg(&g_h0[(b0+b_)*PH + pp_], __ldcg(&h0n_prv[(b0+b_)*PH + pp_]));
        }
        unsigned long long a0 = 0ull, a1 = 0ull, a2 = 0ull, a3 = 0ull;
        if (!khalf){
            int pre = spre[bat];
            float4 x0 = g_xg0[pre*PH + p];
            a0 = pack64(x0.x,0.f); a1 = pack64(x0.y,0.f);
            a2 = pack64(x0.z,0.f); a3 = pack64(x0.w,0.f);
        }
        float fpv = 0.f;
        if (tid < 512){
            int t = stime[batc];
            fpv = __ldcg(&g_Fproj[((size_t)t*BB + b0 + batc)*JH + sub*16 + jlc]);
        }
        STAGE_WAIT();
        {
#pragma unroll 4
            for (int k4 = k4beg; k4 < k4end; k4++){
                ulonglong2 h2 = hrow2[k4];
                int base = k4*40 + lp*2;
                ulonglong2 wa0 = swA2[base+0];
                ulonglong2 wa1 = swA2[base+1];
                ulonglong2 wb0 = swA2[base+20];
                ulonglong2 wb1 = swA2[base+21];
                fma2(a0,h2.x,wa0.x); fma2(a1,h2.x,wa0.y); fma2(a2,h2.x,wa1.x); fma2(a3,h2.x,wa1.y);
                fma2(a0,h2.y,wb0.x); fma2(a1,h2.y,wb0.y); fma2(a2,h2.y,wb1.x); fma2(a3,h2.y,wb1.y);
            }
            if (khalf){
                ppart[tidp*2+0] = make_ulonglong2(a0, a1);
                ppart[tidp*2+1] = make_ulonglong2(a2, a3);
            }
            __syncthreads();
            STAGE_SEL(g_h1, h1n_prv);
            if (tid < 320){
                int b_ = tid/10, pp_ = sub*10 + tid - (tid/10)*10;
                if (snb[b_]) __stcg(&g_h1[(b0+b_)*PH + pp_], __ldcg(&h1n_prv[(b0+b_)*PH + pp_]));
            }
            if (!khalf){
                ulonglong2 q0 = ppart[tidp*2+0], q1 = ppart[tidp*2+1];
                add2(a0, q0.x); add2(a1, q0.y); add2(a2, q1.x); add2(a3, q1.y);
                float l0,h0v,l1,h1v,l2,h2v,l3,h3v;
                unpack64(a0,l0,h0v); unpack64(a1,l1,h1v); unpack64(a2,l2,h2v); unpack64(a3,l3,h3v);
                float gi=l0+h0v, gf=l1+h1v, gg=l2+h2v, go=l3+h3v;
                float cn = sigf(gf)*c0r + sigf(gi)*tanhf(gg);
                float hn = sigf(go)*tanhf(cn);
                c0nr = cn;
                __stcg(&h0n_cur[bgl*PH + p], hn);
            }
        }

        // ============ phase B: LSTM1 (pass0 on old h1) ============
        {
            if (!khalf){
                float4 bv = g_b1r[p];
                a0 = pack64(bv.x,0.f); a1 = pack64(bv.y,0.f);
                a2 = pack64(bv.z,0.f); a3 = pack64(bv.w,0.f);
            } else { a0 = a1 = a2 = a3 = 0ull; }

            STAGE_WAIT();
#pragma unroll 4
            for (int k4 = k4beg; k4 < k4end; k4++){
                ulonglong2 h2 = hrow2[k4];
                int base = k4*40 + lp*2;
                ulonglong2 wa0 = swB22[base+0];
                ulonglong2 wa1 = swB22[base+1];
                ulonglong2 wb0 = swB22[base+20];
                ulonglong2 wb1 = swB22[base+21];
                fma2(a0,h2.x,wa0.x); fma2(a1,h2.x,wa0.y); fma2(a2,h2.x,wa1.x); fma2(a3,h2.x,wa1.y);
                fma2(a0,h2.y,wb0.x); fma2(a1,h2.y,wb0.y); fma2(a2,h2.y,wb1.x); fma2(a3,h2.y,wb1.y);
            }

            barwait(mycnt, myrel, 32u);   // barrier 1: A outputs complete

            STAGE(h0n_cur);
            STAGE_WAIT();
#pragma unroll 4
            for (int k4 = k4beg; k4 < k4end; k4++){
                ulonglong2 h2 = hrow2[k4];
                int base = k4*40 + lp*2;
                ulonglong2 wa0 = swB12[base+0];
                ulonglong2 wa1 = swB12[base+1];
                ulonglong2 wb0 = swB12[base+20];
                ulonglong2 wb1 = swB12[base+21];
                fma2(a0,h2.x,wa0.x); fma2(a1,h2.x,wa0.y); fma2(a2,h2.x,wa1.x); fma2(a3,h2.x,wa1.y);
                fma2(a0,h2.y,wb0.x); fma2(a1,h2.y,wb0.y); fma2(a2,h2.y,wb1.x); fma2(a3,h2.y,wb1.y);
            }
            if (khalf){
                ppart[tidp*2+0] = make_ulonglong2(a0, a1);
                ppart[tidp*2+1] = make_ulonglong2(a2, a3);
            }
            __syncthreads();
            if (!khalf){
                ulonglong2 q0 = ppart[tidp*2+0], q1 = ppart[tidp*2+1];
                add2(a0, q0.x); add2(a1, q0.y); add2(a2, q1.x); add2(a3, q1.y);
                float l0,h0v,l1,h1v,l2,h2v,l3,h3v;
                unpack64(a0,l0,h0v); unpack64(a1,l1,h1v); unpack64(a2,l2,h2v); unpack64(a3,l3,h3v);
                float gi=l0+h0v, gf=l1+h1v, gg=l2+h2v, go=l3+h3v;
                float cn = sigf(gf)*c1r + sigf(gi)*tanhf(gg);
                float hn = sigf(go)*tanhf(cn);
                c1nr = cn;
                __stcg(&h1n_cur[bgl*PH + p], hn);
            }
        }
        barwait(mycnt, myrel, 32u);       // barrier 2: B outputs complete

        // ============ phase C: jrelu slice (smem) + partial logits ============
        STAGE(h1n_cur);
        if (tid == THR-1){
            int fin = 0;
            if (step > 0){
                unsigned d;
                do {
                    asm volatile("ld.acquire.gpu.global.u32 %0,[%1];"
                                 : "=r"(d) : "l"(&g_done[step-1]) : "memory");
                } while (d < (unsigned)BB);
                fin = (__ldcg(&g_eq[step-1]) == (unsigned)BB);
            }
            smnb[1] = fin;
        }
        STAGE_WAIT();
        if (tid < 512){
            unsigned long long p1 = 0ull;
#pragma unroll 4
            for (int k4 = 0; k4 < PH/4; k4++){
                ulonglong2 h2 = hrowc[k4];
                fma2(p1, h2.x, swg2[(2*k4+0)*16 + jlc]);
                fma2(p1, h2.y, swg2[(2*k4+1)*16 + jlc]);
            }
            float lo, hi;
            unpack64(p1, lo, hi);
            float r1 = fpv + (lo + hi);
            ppartf[batc*17 + jlc] = r1 > 0.f ? r1 : 0.f;
        }
        __syncthreads();
        for (int idx = tid; idx < 32*VV; idx += THR){
            int bl_ = idx / VV, v = idx - bl_*VV;
            float s = 0.f;
#pragma unroll
            for (int j = 0; j < 16; j++)
                s = fmaf(ppartf[bl_*17 + j], wos[j*VV + v], s);
            __stcg(&g_lpart[((size_t)(b0 + bl_)*32 + sub)*32 + v], s);
        }
        barwait(mycnt, myrel, 32u);       // barrier 3: lpart complete

        // ============ phase D: REDUNDANT reduce+argmax (all 32 batches per CTA) ============
        if (wrp < 16){
#pragma unroll
            for (int bi = 0; bi < 2; bi++){
                int bq = wrp*2 + bi;
                float s = __int_as_float(0xff800000);
                if (lane < VV){
                    s = sbo[lane];
                    const float* lq = &g_lpart[((size_t)(b0+bq)*32)*32 + lane];
#pragma unroll 8
                    for (int sb = 0; sb < 32; sb++)
                        s += __ldcg(&lq[sb*32]);
                    if (bq == sub){
                        int idx = (step*BB + myb)*VV + lane;
                        if (idx < out_size) out[idx] = s;
                    }
                }
                float val = s; int ix = lane;
#pragma unroll
                for (int off = 16; off > 0; off >>= 1){
                    float ov = __shfl_xor_sync(0xffffffffu, val, off);
                    int   oi = __shfl_xor_sync(0xffffffffu, ix, off);
                    if (ov > val || (ov == val && oi < ix)){ val = ov; ix = oi; }
                }
                if (lane == 0){
                    int sym = ix;
                    int fin = smnb[1];
                    int nb  = (!fin) && (sym != BLANKV);
                    int blk = (!fin) && (sym == BLANKV);
                    snb[bq] = nb;
                    if (nb){
                        int olen = solen[bq];
                        int pos = olen < (MAXL-1) ? olen : (MAXL-1);
                        if (bq == sub) g_tok[myb*MAXL + pos] = sym;
                        solen[bq] = olen + 1;
                        spre[bq] = sym;
                    }
                    int tm  = stime[bq];
                    int eos = seos[bq];
                    if (blk){ tm = tm + 1; if (tm > eos) tm = eos; }
                    stime[bq] = tm;
                    if (bq == sub){
                        if (tm == eos) atomicAdd(&g_eq[step], 1u);
                        unsigned du;
                        asm volatile("atom.add.release.gpu.global.u32 %0,[%1],1;"
                                     : "=r"(du) : "l"(&g_done[step]) : "memory");
                    }
                }
            }
        }
        __syncthreads();   // local only: snb/spre/stime visible for next A
    }

    // final: tokens + out_lens
    if (tid < MAXL){
        int idx = YSN + myb*MAXL + tid;
        if (idx < out_size) out[idx] = (float)g_tok[myb*MAXL + tid];
    }
    if (tid == 0){
        int idx = YSN + BB*MAXL + myb;
        if (idx < out_size) out[idx] = (float)solen[sub];
    }
#undef STAGE_SEL
#undef STAGE
#undef STAGE_WAIT
}

extern "C" void kernel_launch(void* const* d_in, const int* in_sizes, int n_in,
                              void* d_out, int out_size){
    const float* f      = (const float*)d_in[0];
    const int*   f_lens = (const int*)  d_in[1];
    const float* embed  = (const float*)d_in[2];
    const float* w_ih0  = (const float*)d_in[3];
    const float* w_hh0  = (const float*)d_in[4];
    const float* b0     = (const float*)d_in[5];
    const float* w_ih1  = (const float*)d_in[6];
    const float* w_hh1  = (const float*)d_in[7];
    const float* b1     = (const float*)d_in[8];
    const float* w_f    = (const float*)d_in[9];
    const float* w_g    = (const float*)d_in[10];
    const float* b_j    = (const float*)d_in[11];
    const float* w_o    = (const float*)d_in[12];
    const float* b_o    = (const float*)d_in[13];
    float* out = (float*)d_out;

    const int smem_bytes = 3*51200 + 20480 + SMH_F*4 + 640*16 + 16*VV*4 + 6*32*4 + 64;
    cudaFuncSetAttribute(decode_kernel, cudaFuncAttributeMaxDynamicSharedMemorySize, smem_bytes);

    rearr_init_kernel<<<1600, 256>>>(w_hh0, w_ih1, w_hh1, b1);
    xg0_kernel<<<VV, 256>>>(embed, w_ih0, b0);
    fproj_kernel<<<dim3(JH/64, (TT*BB)/128), 256>>>(f, w_f, b_j);
    decode_kernel<<<BB, THR, smem_bytes>>>(f_lens, w_g, w_o, b_o, out, out_size);
}